// round 1
// baseline (speedup 1.0000x reference)
#include <cuda_runtime.h>
#include <math.h>

#define BB 2
#define NTOK 2048
#define DD 512
#define HH 8
#define DHH 64
#define HIDN 2730
#define HID2 1365
#define HS_LD 1368
#define MTOT (BB*NTOK)   // 4096

// ---------------- scratch (static device globals; no runtime allocation) ----
__device__ float g_xn  [MTOT*DD];
__device__ float g_q   [MTOT*DD];
__device__ float g_k   [MTOT*DD];
__device__ float g_v   [MTOT*DD];
__device__ float g_ctx [MTOT*DD];
__device__ float g_x1  [MTOT*DD];
__device__ float g_xn2 [MTOT*DD];
__device__ float g_hpre[(size_t)MTOT*HIDN];
__device__ float g_hs  [(size_t)MTOT*HS_LD];

// ---------------- LayerNorm: one block per row of 512 ----------------------
__global__ void ln_kernel(const float* __restrict__ x,
                          const float* __restrict__ w,
                          const float* __restrict__ b,
                          float* __restrict__ out) {
    int row = blockIdx.x;
    int t = threadIdx.x;  // 128 threads, 4 floats each
    const float4* xr = (const float4*)(x + (size_t)row * DD);
    float4 v = xr[t];
    float s  = v.x + v.y + v.z + v.w;
    float sq = v.x*v.x + v.y*v.y + v.z*v.z + v.w*v.w;
    #pragma unroll
    for (int o = 16; o; o >>= 1) {
        s  += __shfl_xor_sync(0xffffffffu, s,  o);
        sq += __shfl_xor_sync(0xffffffffu, sq, o);
    }
    __shared__ float ss[4], ssq[4];
    if ((t & 31) == 0) { ss[t >> 5] = s; ssq[t >> 5] = sq; }
    __syncthreads();
    s  = ss[0] + ss[1] + ss[2] + ss[3];
    sq = ssq[0] + ssq[1] + ssq[2] + ssq[3];
    float mean = s * (1.0f / DD);
    float var  = sq * (1.0f / DD) - mean * mean;
    float rstd = rsqrtf(var + 1e-5f);
    float4 wv = ((const float4*)w)[t];
    float4 bv = ((const float4*)b)[t];
    float4 o4;
    o4.x = (v.x - mean) * rstd * wv.x + bv.x;
    o4.y = (v.y - mean) * rstd * wv.y + bv.y;
    o4.z = (v.z - mean) * rstd * wv.z + bv.z;
    o4.w = (v.w - mean) * rstd * wv.w + bv.w;
    ((float4*)(out + (size_t)row * DD))[t] = o4;
}

// ---------------- generic NT GEMM: C[m,n] = sum_k A[m,k]*Bw[n,k] + bias[n] --
// MODE 0: plain.  MODE 1: C = res[m,n] + gamma[n]*(dot+bias)
template<int MODE>
__global__ void __launch_bounds__(256) gemm_nt(
    const float* __restrict__ A, int lda,
    const float* __restrict__ Bw, int ldb,
    const float* __restrict__ bias,
    float* __restrict__ C, int ldc,
    int M, int Nc, int K,
    const float* __restrict__ res, const float* __restrict__ gamma)
{
    __shared__ float As[16][129];
    __shared__ float Bs[16][65];
    int bm = blockIdx.y * 128;
    int bn = blockIdx.x * 64;
    int t  = threadIdx.x;
    int tx = t & 15, ty = t >> 4;     // compute layout: 16x16, micro 8x4
    int kj  = t & 15;                  // k offset for loads
    int ri  = t >> 4;                  // row group for loads

    float acc[8][4];
    #pragma unroll
    for (int i = 0; i < 8; i++)
        #pragma unroll
        for (int j = 0; j < 4; j++) acc[i][j] = 0.0f;

    for (int k0 = 0; k0 < K; k0 += 16) {
        int kk = k0 + kj;
        bool kok = (kk < K);
        #pragma unroll
        for (int p = 0; p < 8; p++) {
            int mrow = bm + ri + p * 16;
            As[kj][ri + p * 16] = kok ? A[(size_t)mrow * lda + kk] : 0.0f;
        }
        #pragma unroll
        for (int p = 0; p < 4; p++) {
            int nrow = bn + ri + p * 16;
            Bs[kj][ri + p * 16] = (kok && nrow < Nc) ? Bw[(size_t)nrow * ldb + kk] : 0.0f;
        }
        __syncthreads();
        #pragma unroll
        for (int q = 0; q < 16; q++) {
            float a[8], bv[4];
            #pragma unroll
            for (int i = 0; i < 8; i++) a[i] = As[q][ty * 8 + i];
            #pragma unroll
            for (int j = 0; j < 4; j++) bv[j] = Bs[q][tx * 4 + j];
            #pragma unroll
            for (int i = 0; i < 8; i++)
                #pragma unroll
                for (int j = 0; j < 4; j++)
                    acc[i][j] += a[i] * bv[j];
        }
        __syncthreads();
    }
    #pragma unroll
    for (int i = 0; i < 8; i++) {
        int m = bm + ty * 8 + i;
        #pragma unroll
        for (int j = 0; j < 4; j++) {
            int n = bn + tx * 4 + j;
            if (n < Nc) {
                float vl = acc[i][j] + bias[n];
                if (MODE == 1) vl = res[(size_t)m * ldc + n] + gamma[n] * vl;
                C[(size_t)m * ldc + n] = vl;
            }
        }
    }
}

// ---------------- flash attention with distance-ALiBi bias ------------------
// grid: (NTOK/128, H, B), 128 threads; each thread owns one query row.
__global__ void __launch_bounds__(128) attn_kernel(
    const float* __restrict__ q, const float* __restrict__ k,
    const float* __restrict__ v, const float* __restrict__ coords,
    float* __restrict__ ctx)
{
    int b = blockIdx.z, h = blockIdx.y;
    int m = blockIdx.x * 128 + threadIdx.x;

    const float scale = 0.125f;  // 1/sqrt(64)
    float slope = exp2f(-(float)(h + 1));

    float qr[64];
    {
        const float4* qrow = (const float4*)(q + ((size_t)(b * NTOK + m)) * DD + h * DHH);
        #pragma unroll
        for (int i = 0; i < 16; i++) {
            float4 tq = qrow[i];
            qr[i*4+0] = tq.x * scale; qr[i*4+1] = tq.y * scale;
            qr[i*4+2] = tq.z * scale; qr[i*4+3] = tq.w * scale;
        }
    }
    float2 qc = *(const float2*)(coords + ((size_t)(b * NTOK + m)) * 2);

    float mi = -1e30f, li = 0.0f;
    float acc[64];
    #pragma unroll
    for (int i = 0; i < 64; i++) acc[i] = 0.0f;

    __shared__ float Ks[64][64];
    __shared__ float Vs[64][64];
    __shared__ float kcx[64], kcy[64];

    int lr   = threadIdx.x >> 1;       // row 0..63
    int half = threadIdx.x & 1;        // half-row

    for (int kt = 0; kt < NTOK; kt += 64) {
        __syncthreads();
        {
            const float4* krow = (const float4*)(k + ((size_t)(b * NTOK + kt + lr)) * DD + h * DHH + half * 32);
            const float4* vrow = (const float4*)(v + ((size_t)(b * NTOK + kt + lr)) * DD + h * DHH + half * 32);
            float4* kd = (float4*)&Ks[lr][half * 32];
            float4* vd = (float4*)&Vs[lr][half * 32];
            #pragma unroll
            for (int i = 0; i < 8; i++) { kd[i] = krow[i]; vd[i] = vrow[i]; }
            if (threadIdx.x < 64) {
                float2 c = *(const float2*)(coords + ((size_t)(b * NTOK + kt + threadIdx.x)) * 2);
                kcx[threadIdx.x] = c.x; kcy[threadIdx.x] = c.y;
            }
        }
        __syncthreads();

        for (int j0 = 0; j0 < 64; j0 += 16) {
            float s[16];
            #pragma unroll
            for (int jj = 0; jj < 16; jj++) {
                int j = j0 + jj;
                float dot = 0.0f;
                #pragma unroll
                for (int d = 0; d < 64; d += 4) {
                    float4 kv = *(const float4*)&Ks[j][d];
                    dot += qr[d] * kv.x + qr[d+1] * kv.y + qr[d+2] * kv.z + qr[d+3] * kv.w;
                }
                float dx = qc.x - kcx[j], dy = qc.y - kcy[j];
                s[jj] = dot - slope * sqrtf(dx * dx + dy * dy);
            }
            float mnew = mi;
            #pragma unroll
            for (int jj = 0; jj < 16; jj++) mnew = fmaxf(mnew, s[jj]);
            float corr = __expf(mi - mnew);
            mi = mnew;
            li *= corr;
            #pragma unroll
            for (int d = 0; d < 64; d++) acc[d] *= corr;
            #pragma unroll
            for (int jj = 0; jj < 16; jj++) {
                float p = __expf(s[jj] - mi);
                li += p;
                #pragma unroll
                for (int d = 0; d < 64; d += 4) {
                    float4 vv = *(const float4*)&Vs[j0 + jj][d];
                    acc[d]   += p * vv.x;
                    acc[d+1] += p * vv.y;
                    acc[d+2] += p * vv.z;
                    acc[d+3] += p * vv.w;
                }
            }
        }
    }
    float inv = 1.0f / li;
    float4* crow = (float4*)(ctx + ((size_t)(b * NTOK + m)) * DD + h * DHH);
    #pragma unroll
    for (int i = 0; i < 16; i++) {
        float4 o4;
        o4.x = acc[i*4+0] * inv; o4.y = acc[i*4+1] * inv;
        o4.z = acc[i*4+2] * inv; o4.w = acc[i*4+3] * inv;
        crow[i] = o4;
    }
}

// ---------------- SwiGLU elementwise ---------------------------------------
__global__ void swiglu_kernel(const float* __restrict__ hpre, float* __restrict__ hs) {
    int idx = blockIdx.x * 256 + threadIdx.x;
    if (idx >= MTOT * HID2) return;
    int m = idx / HID2;
    int j = idx - m * HID2;
    float h1 = hpre[(size_t)m * HIDN + j];
    float h2 = hpre[(size_t)m * HIDN + HID2 + j];
    float sg = 1.0f / (1.0f + __expf(-h1));
    hs[(size_t)m * HS_LD + j] = h1 * sg * h2;
}

// ---------------- launcher --------------------------------------------------
extern "C" void kernel_launch(void* const* d_in, const int* in_sizes, int n_in,
                              void* d_out, int out_size) {
    (void)in_sizes; (void)n_in; (void)out_size;
    const float* x      = (const float*)d_in[0];
    const float* coords = (const float*)d_in[1];
    const float* q_w    = (const float*)d_in[2];
    const float* q_b    = (const float*)d_in[3];
    const float* k_w    = (const float*)d_in[4];
    const float* k_b    = (const float*)d_in[5];
    const float* v_w    = (const float*)d_in[6];
    const float* v_b    = (const float*)d_in[7];
    const float* o_w    = (const float*)d_in[8];
    const float* o_b    = (const float*)d_in[9];
    const float* gamma1 = (const float*)d_in[10];
    const float* ln1_w  = (const float*)d_in[11];
    const float* ln1_b  = (const float*)d_in[12];
    const float* fc1_w  = (const float*)d_in[13];
    const float* fc1_b  = (const float*)d_in[14];
    const float* fc2_w  = (const float*)d_in[15];
    const float* fc2_b  = (const float*)d_in[16];
    const float* gamma2 = (const float*)d_in[17];
    const float* ln2_w  = (const float*)d_in[18];
    const float* ln2_b  = (const float*)d_in[19];
    float* out = (float*)d_out;

    float *xn, *q, *k, *v, *ctx, *x1, *xn2, *hpre, *hs;
    cudaGetSymbolAddress((void**)&xn,   g_xn);
    cudaGetSymbolAddress((void**)&q,    g_q);
    cudaGetSymbolAddress((void**)&k,    g_k);
    cudaGetSymbolAddress((void**)&v,    g_v);
    cudaGetSymbolAddress((void**)&ctx,  g_ctx);
    cudaGetSymbolAddress((void**)&x1,   g_x1);
    cudaGetSymbolAddress((void**)&xn2,  g_xn2);
    cudaGetSymbolAddress((void**)&hpre, g_hpre);
    cudaGetSymbolAddress((void**)&hs,   g_hs);

    // LN1
    ln_kernel<<<MTOT, 128>>>(x, ln1_w, ln1_b, xn);

    // QKV projections
    dim3 gproj((DD + 63) / 64, MTOT / 128);
    gemm_nt<0><<<gproj, 256>>>(xn, DD, q_w, DD, q_b, q, DD, MTOT, DD, DD, nullptr, nullptr);
    gemm_nt<0><<<gproj, 256>>>(xn, DD, k_w, DD, k_b, k, DD, MTOT, DD, DD, nullptr, nullptr);
    gemm_nt<0><<<gproj, 256>>>(xn, DD, v_w, DD, v_b, v, DD, MTOT, DD, DD, nullptr, nullptr);

    // flash attention w/ distance ALiBi
    dim3 gattn(NTOK / 128, HH, BB);
    attn_kernel<<<gattn, 128>>>(q, k, v, coords, ctx);

    // O projection + residual1
    gemm_nt<1><<<gproj, 256>>>(ctx, DD, o_w, DD, o_b, x1, DD, MTOT, DD, DD, x, gamma1);

    // LN2
    ln_kernel<<<MTOT, 128>>>(x1, ln2_w, ln2_b, xn2);

    // fc1 (HID=2730 outputs)
    dim3 gfc1((HIDN + 63) / 64, MTOT / 128);
    gemm_nt<0><<<gfc1, 256>>>(xn2, DD, fc1_w, DD, fc1_b, hpre, HIDN, MTOT, HIDN, DD, nullptr, nullptr);

    // SwiGLU
    int nsw = MTOT * HID2;
    swiglu_kernel<<<(nsw + 255) / 256, 256>>>(hpre, hs);

    // fc2 + residual2 -> d_out
    gemm_nt<1><<<gproj, 256>>>(hs, HS_LD, fc2_w, HID2, fc2_b, out, DD, MTOT, DD, HID2, x1, gamma2);
}

// round 6
// speedup vs baseline: 1.6801x; 1.6801x over previous
#include <cuda_runtime.h>
#include <cuda_bf16.h>
#include <cstdint>
#include <math.h>

#define BB 2
#define NTOK 2048
#define DD 512
#define HH 8
#define DHH 64
#define HIDN 2730
#define HID2 1365
#define HID2P 1408     // padded K for fc2
#define HIDNP 2816     // padded N for fc1 weights
#define MTOT (BB*NTOK) // 4096

// ---------------- scratch (static device globals) ---------------------------
__device__ __nv_bfloat16 g_xn_bf [MTOT*DD];
__device__ __nv_bfloat16 g_xn2_bf[MTOT*DD];
__device__ __nv_bfloat16 g_ctx_bf[MTOT*DD];
__device__ __nv_bfloat16 g_wq_bf [DD*DD];
__device__ __nv_bfloat16 g_wk_bf [DD*DD];
__device__ __nv_bfloat16 g_wv_bf [DD*DD];
__device__ __nv_bfloat16 g_wo_bf [DD*DD];
__device__ __nv_bfloat16 g_fc1w_bf[(size_t)HIDNP*DD];
__device__ __nv_bfloat16 g_fc2w_bf[(size_t)DD*HID2P];
__device__ __nv_bfloat16 g_hs_bf  [(size_t)MTOT*HID2P];
__device__ float g_q   [MTOT*DD];
__device__ float g_k   [MTOT*DD];
__device__ float g_v   [MTOT*DD];
__device__ float g_x1  [MTOT*DD];
__device__ float g_hpre[(size_t)MTOT*HIDN];

// ---------------- base-ISA helpers ------------------------------------------
__device__ __forceinline__ uint32_t smem_to_u32(const void* p) {
    uint32_t a;
    asm("{ .reg .u64 t; cvta.to.shared.u64 t, %1; cvt.u32.u64 %0, t; }"
        : "=r"(a) : "l"(p));
    return a;
}
#define SMEM_SWIZZLE_128B(o) ((o) ^ (((o) >> 3) & 0x70))

__device__ __forceinline__ void cp_async16(uint32_t saddr, const void* gptr) {
    asm volatile("cp.async.cg.shared.global [%0], [%1], 16;"
                 :: "r"(saddr), "l"(gptr));
}
__device__ __forceinline__ void ldmatrix_x4(uint32_t& r0, uint32_t& r1,
                                            uint32_t& r2, uint32_t& r3,
                                            uint32_t addr) {
    asm volatile("ldmatrix.sync.aligned.m8n8.x4.shared.b16 {%0,%1,%2,%3}, [%4];"
                 : "=r"(r0), "=r"(r1), "=r"(r2), "=r"(r3) : "r"(addr));
}
__device__ __forceinline__ void mma_bf16(float* c,
                                         uint32_t a0, uint32_t a1, uint32_t a2, uint32_t a3,
                                         uint32_t b0, uint32_t b1) {
    asm volatile(
        "mma.sync.aligned.m16n8k16.row.col.f32.bf16.bf16.f32 "
        "{%0,%1,%2,%3}, {%4,%5,%6,%7}, {%8,%9}, {%0,%1,%2,%3};"
        : "+f"(c[0]), "+f"(c[1]), "+f"(c[2]), "+f"(c[3])
        : "r"(a0), "r"(a1), "r"(a2), "r"(a3), "r"(b0), "r"(b1));
}

// ---------------- bf16 warp-MMA NT GEMM -------------------------------------
// C[M,N] = A[M,K] * Bw[N,K]^T + bias[N]    A,Bw bf16 K-major, C fp32
// mode 0: plain  mode 1: C = res + gamma * (dot + bias)
// K multiple of 64. Bw must have >= gridDim.x*64 rows (zero-padded).
// CTA 128x64, BK=64, 8 warps (2m x 4n), warp tile 64x16,
// double-buffered cp.async: 2 stages x (16KB A + 8KB B) = 49152B = 48KB cap.
__global__ void __launch_bounds__(256) gemm_mma(
    const __nv_bfloat16* __restrict__ A,
    const __nv_bfloat16* __restrict__ Bw,
    const float* __restrict__ bias,
    float* __restrict__ C, int ldc, int Nc, int K,
    const float* __restrict__ res, const float* __restrict__ gamma, int mode)
{
    extern __shared__ char smem[];
    uint32_t sbase = smem_to_u32(smem);
    const int tid = threadIdx.x, lane = tid & 31, wid = tid >> 5;
    const int wm = wid & 1, wn = wid >> 1;          // warp grid 2(m) x 4(n)
    const int bm = blockIdx.y * 128, bn = blockIdx.x * 64;

    const uint32_t STAGE = 24576u;  // 16KB A + 8KB B
    const uint32_t BOFF  = 16384u;

    float acc[4][2][4];
    #pragma unroll
    for (int i = 0; i < 4; i++)
        #pragma unroll
        for (int j = 0; j < 2; j++)
            #pragma unroll
            for (int t = 0; t < 4; t++) acc[i][j][t] = 0.0f;

    const int lrow = tid >> 3;     // 0..31 (load row group)
    const int lcol = tid & 7;      // 16B unit within 128B row
    const int nch  = K >> 6;       // chunks of 64 bf16

    // ldmatrix lane addressing
    const int arow  = wm * 64 + (lane & 15);
    const int akoff = lane >> 4;                       // 0/1 -> k0/k8 16B unit
    const int brow  = wn * 16 + (lane & 7) + ((lane >> 4) << 3);
    const int bkoff = (lane >> 3) & 1;

    auto issue = [&](int c, int s) {
        uint32_t sb = sbase + (uint32_t)s * STAGE;
        #pragma unroll
        for (int i = 0; i < 4; i++) {       // A: 128 rows
            int r = lrow + i * 32;
            uint32_t off = SMEM_SWIZZLE_128B((uint32_t)(r * 128 + lcol * 16));
            cp_async16(sb + off, A + (size_t)(bm + r) * K + c * 64 + lcol * 8);
        }
        #pragma unroll
        for (int i = 0; i < 2; i++) {       // B: 64 rows
            int r = lrow + i * 32;
            uint32_t off = SMEM_SWIZZLE_128B((uint32_t)(r * 128 + lcol * 16));
            cp_async16(sb + BOFF + off, Bw + (size_t)(bn + r) * K + c * 64 + lcol * 8);
        }
        asm volatile("cp.async.commit_group;" ::: "memory");
    };

    issue(0, 0);
    for (int c = 0; c < nch; c++) {
        int s = c & 1;
        if (c + 1 < nch) {
            issue(c + 1, (c + 1) & 1);
            asm volatile("cp.async.wait_group 1;" ::: "memory");
        } else {
            asm volatile("cp.async.wait_group 0;" ::: "memory");
        }
        __syncthreads();

        uint32_t sa  = sbase + (uint32_t)s * STAGE;
        uint32_t sbb = sa + BOFF;
        #pragma unroll
        for (int ks = 0; ks < 4; ks++) {
            uint32_t a[4][4], b[4];
            #pragma unroll
            for (int mi = 0; mi < 4; mi++) {
                int r = arow + mi * 16;
                uint32_t addr = sa + SMEM_SWIZZLE_128B(
                    (uint32_t)(r * 128 + (2 * ks + akoff) * 16));
                ldmatrix_x4(a[mi][0], a[mi][1], a[mi][2], a[mi][3], addr);
            }
            {
                uint32_t addr = sbb + SMEM_SWIZZLE_128B(
                    (uint32_t)(brow * 128 + (2 * ks + bkoff) * 16));
                ldmatrix_x4(b[0], b[1], b[2], b[3], addr);
            }
            #pragma unroll
            for (int mi = 0; mi < 4; mi++) {
                mma_bf16(acc[mi][0], a[mi][0], a[mi][1], a[mi][2], a[mi][3], b[0], b[1]);
                mma_bf16(acc[mi][1], a[mi][0], a[mi][1], a[mi][2], a[mi][3], b[2], b[3]);
            }
        }
        __syncthreads();
    }

    // epilogue: thread owns (row, col..col+1) and (row+8, col..col+1) per tile
    int rbase = bm + wm * 64 + (lane >> 2);
    int cbase = bn + wn * 16 + 2 * (lane & 3);
    #pragma unroll
    for (int mi = 0; mi < 4; mi++) {
        int r0 = rbase + mi * 16;
        #pragma unroll
        for (int ni = 0; ni < 2; ni++) {
            int n0 = cbase + ni * 8;
            if (n0 < Nc) {
                float b0 = bias[n0], b1 = bias[n0 + 1];
                float v0 = acc[mi][ni][0] + b0, v1 = acc[mi][ni][1] + b1;
                float v2 = acc[mi][ni][2] + b0, v3 = acc[mi][ni][3] + b1;
                if (mode) {
                    float g0 = gamma[n0], g1 = gamma[n0 + 1];
                    v0 = res[(size_t)r0 * ldc + n0]           + g0 * v0;
                    v1 = res[(size_t)r0 * ldc + n0 + 1]       + g1 * v1;
                    v2 = res[(size_t)(r0 + 8) * ldc + n0]     + g0 * v2;
                    v3 = res[(size_t)(r0 + 8) * ldc + n0 + 1] + g1 * v3;
                }
                *(float2*)&C[(size_t)r0 * ldc + n0]       = make_float2(v0, v1);
                *(float2*)&C[(size_t)(r0 + 8) * ldc + n0] = make_float2(v2, v3);
            }
        }
    }
}

// ---------------- LayerNorm -> bf16 -----------------------------------------
__global__ void ln_bf16_kernel(const float* __restrict__ x,
                               const float* __restrict__ w,
                               const float* __restrict__ b,
                               __nv_bfloat16* __restrict__ out) {
    int row = blockIdx.x;
    int t = threadIdx.x;  // 128 threads, 4 floats each
    const float4* xr = (const float4*)(x + (size_t)row * DD);
    float4 v = xr[t];
    float s  = v.x + v.y + v.z + v.w;
    float sq = v.x*v.x + v.y*v.y + v.z*v.z + v.w*v.w;
    #pragma unroll
    for (int o = 16; o; o >>= 1) {
        s  += __shfl_xor_sync(0xffffffffu, s,  o);
        sq += __shfl_xor_sync(0xffffffffu, sq, o);
    }
    __shared__ float ss[4], ssq[4];
    if ((t & 31) == 0) { ss[t >> 5] = s; ssq[t >> 5] = sq; }
    __syncthreads();
    s  = ss[0] + ss[1] + ss[2] + ss[3];
    sq = ssq[0] + ssq[1] + ssq[2] + ssq[3];
    float mean = s * (1.0f / DD);
    float var  = sq * (1.0f / DD) - mean * mean;
    float rstd = rsqrtf(var + 1e-5f);
    float4 wv = ((const float4*)w)[t];
    float4 bv = ((const float4*)b)[t];
    float o0 = (v.x - mean) * rstd * wv.x + bv.x;
    float o1 = (v.y - mean) * rstd * wv.y + bv.y;
    float o2 = (v.z - mean) * rstd * wv.z + bv.z;
    float o3 = (v.w - mean) * rstd * wv.w + bv.w;
    __nv_bfloat162* orow = (__nv_bfloat162*)(out + (size_t)row * DD);
    orow[t * 2]     = __floats2bfloat162_rn(o0, o1);
    orow[t * 2 + 1] = __floats2bfloat162_rn(o2, o3);
}

// ---------------- weight fp32 -> bf16 (with padding) ------------------------
__global__ void conv_w_kernel(const float* __restrict__ src, __nv_bfloat16* __restrict__ dst,
                              int N, int K, int Npad, int Kpad) {
    size_t idx = (size_t)blockIdx.x * 256 + threadIdx.x;
    size_t total = (size_t)Npad * Kpad;
    if (idx >= total) return;
    int n = (int)(idx / Kpad);
    int k = (int)(idx - (size_t)n * Kpad);
    float v = (n < N && k < K) ? src[(size_t)n * K + k] : 0.0f;
    dst[idx] = __float2bfloat16(v);
}

// ---------------- flash attention with distance-ALiBi bias ------------------
__global__ void __launch_bounds__(128) attn_kernel(
    const float* __restrict__ q, const float* __restrict__ k,
    const float* __restrict__ v, const float* __restrict__ coords,
    __nv_bfloat16* __restrict__ ctx)
{
    int b = blockIdx.z, h = blockIdx.y;
    int m = blockIdx.x * 128 + threadIdx.x;

    const float scale = 0.125f;
    float slope = exp2f(-(float)(h + 1));

    float qr[64];
    {
        const float4* qrow = (const float4*)(q + ((size_t)(b * NTOK + m)) * DD + h * DHH);
        #pragma unroll
        for (int i = 0; i < 16; i++) {
            float4 tq = qrow[i];
            qr[i*4+0] = tq.x * scale; qr[i*4+1] = tq.y * scale;
            qr[i*4+2] = tq.z * scale; qr[i*4+3] = tq.w * scale;
        }
    }
    float2 qc = *(const float2*)(coords + ((size_t)(b * NTOK + m)) * 2);

    float mi = -1e30f, li = 0.0f;
    float acc[64];
    #pragma unroll
    for (int i = 0; i < 64; i++) acc[i] = 0.0f;

    __shared__ float Ks[64][64];
    __shared__ float Vs[64][64];
    __shared__ float kcx[64], kcy[64];

    int lr   = threadIdx.x >> 1;
    int half = threadIdx.x & 1;

    for (int kt = 0; kt < NTOK; kt += 64) {
        __syncthreads();
        {
            const float4* krow = (const float4*)(k + ((size_t)(b * NTOK + kt + lr)) * DD + h * DHH + half * 32);
            const float4* vrow = (const float4*)(v + ((size_t)(b * NTOK + kt + lr)) * DD + h * DHH + half * 32);
            float4* kd = (float4*)&Ks[lr][half * 32];
            float4* vd = (float4*)&Vs[lr][half * 32];
            #pragma unroll
            for (int i = 0; i < 8; i++) { kd[i] = krow[i]; vd[i] = vrow[i]; }
            if (threadIdx.x < 64) {
                float2 c = *(const float2*)(coords + ((size_t)(b * NTOK + kt + threadIdx.x)) * 2);
                kcx[threadIdx.x] = c.x; kcy[threadIdx.x] = c.y;
            }
        }
        __syncthreads();

        for (int j0 = 0; j0 < 64; j0 += 16) {
            float s[16];
            #pragma unroll
            for (int jj = 0; jj < 16; jj++) {
                int j = j0 + jj;
                float dot = 0.0f;
                #pragma unroll
                for (int d = 0; d < 64; d += 4) {
                    float4 kv = *(const float4*)&Ks[j][d];
                    dot += qr[d] * kv.x + qr[d+1] * kv.y + qr[d+2] * kv.z + qr[d+3] * kv.w;
                }
                float dx = qc.x - kcx[j], dy = qc.y - kcy[j];
                s[jj] = dot - slope * sqrtf(dx * dx + dy * dy);
            }
            float mnew = mi;
            #pragma unroll
            for (int jj = 0; jj < 16; jj++) mnew = fmaxf(mnew, s[jj]);
            float corr = __expf(mi - mnew);
            mi = mnew;
            li *= corr;
            #pragma unroll
            for (int d = 0; d < 64; d++) acc[d] *= corr;
            #pragma unroll
            for (int jj = 0; jj < 16; jj++) {
                float p = __expf(s[jj] - mi);
                li += p;
                #pragma unroll
                for (int d = 0; d < 64; d += 4) {
                    float4 vv = *(const float4*)&Vs[j0 + jj][d];
                    acc[d]   += p * vv.x;
                    acc[d+1] += p * vv.y;
                    acc[d+2] += p * vv.z;
                    acc[d+3] += p * vv.w;
                }
            }
        }
    }
    float inv = 1.0f / li;
    __nv_bfloat162* crow = (__nv_bfloat162*)(ctx + ((size_t)(b * NTOK + m)) * DD + h * DHH);
    #pragma unroll
    for (int i = 0; i < 32; i++) {
        crow[i] = __floats2bfloat162_rn(acc[i*2] * inv, acc[i*2+1] * inv);
    }
}

// ---------------- SwiGLU -> bf16 (padded) -----------------------------------
__global__ void swiglu_kernel(const float* __restrict__ hpre, __nv_bfloat16* __restrict__ hs) {
    size_t idx = (size_t)blockIdx.x * 256 + threadIdx.x;
    if (idx >= (size_t)MTOT * HID2P) return;
    int m = (int)(idx / HID2P);
    int j = (int)(idx - (size_t)m * HID2P);
    float val = 0.0f;
    if (j < HID2) {
        float h1 = hpre[(size_t)m * HIDN + j];
        float h2 = hpre[(size_t)m * HIDN + HID2 + j];
        float sg = 1.0f / (1.0f + __expf(-h1));
        val = h1 * sg * h2;
    }
    hs[idx] = __float2bfloat16(val);
}

// ---------------- launcher --------------------------------------------------
extern "C" void kernel_launch(void* const* d_in, const int* in_sizes, int n_in,
                              void* d_out, int out_size) {
    (void)in_sizes; (void)n_in; (void)out_size;
    const float* x      = (const float*)d_in[0];
    const float* coords = (const float*)d_in[1];
    const float* q_w    = (const float*)d_in[2];
    const float* q_b    = (const float*)d_in[3];
    const float* k_w    = (const float*)d_in[4];
    const float* k_b    = (const float*)d_in[5];
    const float* v_w    = (const float*)d_in[6];
    const float* v_b    = (const float*)d_in[7];
    const float* o_w    = (const float*)d_in[8];
    const float* o_b    = (const float*)d_in[9];
    const float* gamma1 = (const float*)d_in[10];
    const float* ln1_w  = (const float*)d_in[11];
    const float* ln1_b  = (const float*)d_in[12];
    const float* fc1_w  = (const float*)d_in[13];
    const float* fc1_b  = (const float*)d_in[14];
    const float* fc2_w  = (const float*)d_in[15];
    const float* fc2_b  = (const float*)d_in[16];
    const float* gamma2 = (const float*)d_in[17];
    const float* ln2_w  = (const float*)d_in[18];
    const float* ln2_b  = (const float*)d_in[19];
    float* out = (float*)d_out;

    __nv_bfloat16 *xn, *xn2, *ctxb, *wq, *wk, *wv, *wo, *fc1w, *fc2w, *hsb;
    float *q, *k, *v, *x1, *hpre;
    cudaGetSymbolAddress((void**)&xn,   g_xn_bf);
    cudaGetSymbolAddress((void**)&xn2,  g_xn2_bf);
    cudaGetSymbolAddress((void**)&ctxb, g_ctx_bf);
    cudaGetSymbolAddress((void**)&wq,   g_wq_bf);
    cudaGetSymbolAddress((void**)&wk,   g_wk_bf);
    cudaGetSymbolAddress((void**)&wv,   g_wv_bf);
    cudaGetSymbolAddress((void**)&wo,   g_wo_bf);
    cudaGetSymbolAddress((void**)&fc1w, g_fc1w_bf);
    cudaGetSymbolAddress((void**)&fc2w, g_fc2w_bf);
    cudaGetSymbolAddress((void**)&hsb,  g_hs_bf);
    cudaGetSymbolAddress((void**)&q,    g_q);
    cudaGetSymbolAddress((void**)&k,    g_k);
    cudaGetSymbolAddress((void**)&v,    g_v);
    cudaGetSymbolAddress((void**)&x1,   g_x1);
    cudaGetSymbolAddress((void**)&hpre, g_hpre);

    const int SMEM_GEMM = 49152;  // 2 stages x (16KB A + 8KB B) = default cap

    // weight conversions (bf16, padded)
    {
        int n1 = DD * DD;
        conv_w_kernel<<<(n1 + 255) / 256, 256>>>(q_w, wq, DD, DD, DD, DD);
        conv_w_kernel<<<(n1 + 255) / 256, 256>>>(k_w, wk, DD, DD, DD, DD);
        conv_w_kernel<<<(n1 + 255) / 256, 256>>>(v_w, wv, DD, DD, DD, DD);
        conv_w_kernel<<<(n1 + 255) / 256, 256>>>(o_w, wo, DD, DD, DD, DD);
        size_t n2 = (size_t)HIDNP * DD;
        conv_w_kernel<<<(int)((n2 + 255) / 256), 256>>>(fc1_w, fc1w, HIDN, DD, HIDNP, DD);
        size_t n3 = (size_t)DD * HID2P;
        conv_w_kernel<<<(int)((n3 + 255) / 256), 256>>>(fc2_w, fc2w, DD, HID2, DD, HID2P);
    }

    // LN1 -> bf16
    ln_bf16_kernel<<<MTOT, 128>>>(x, ln1_w, ln1_b, xn);

    // QKV projections (warp MMA)
    dim3 gproj(DD / 64, MTOT / 128);
    gemm_mma<<<gproj, 256, SMEM_GEMM>>>(xn, wq, q_b, q, DD, DD, DD, nullptr, nullptr, 0);
    gemm_mma<<<gproj, 256, SMEM_GEMM>>>(xn, wk, k_b, k, DD, DD, DD, nullptr, nullptr, 0);
    gemm_mma<<<gproj, 256, SMEM_GEMM>>>(xn, wv, v_b, v, DD, DD, DD, nullptr, nullptr, 0);

    // flash attention (fp32 SIMT, bf16 output)
    dim3 gattn(NTOK / 128, HH, BB);
    attn_kernel<<<gattn, 128>>>(q, k, v, coords, ctxb);

    // O projection + residual1
    gemm_mma<<<gproj, 256, SMEM_GEMM>>>(ctxb, wo, o_b, x1, DD, DD, DD, x, gamma1, 1);

    // LN2 -> bf16
    ln_bf16_kernel<<<MTOT, 128>>>(x1, ln2_w, ln2_b, xn2);

    // fc1
    dim3 gfc1(HIDNP / 64, MTOT / 128);
    gemm_mma<<<gfc1, 256, SMEM_GEMM>>>(xn2, fc1w, fc1_b, hpre, HIDN, HIDN, DD, nullptr, nullptr, 0);

    // SwiGLU -> bf16 padded
    size_t nsw = (size_t)MTOT * HID2P;
    swiglu_kernel<<<(int)((nsw + 255) / 256), 256>>>(hpre, hsb);

    // fc2 + residual2 -> out
    gemm_mma<<<gproj, 256, SMEM_GEMM>>>(hsb, fc2w, fc2_b, out, DD, DD, HID2P, x1, gamma2, 1);
}

// round 7
// speedup vs baseline: 5.3801x; 3.2023x over previous
#include <cuda_runtime.h>
#include <cuda_bf16.h>
#include <cstdint>
#include <math.h>

#define BB 2
#define NTOK 2048
#define DD 512
#define HH 8
#define DHH 64
#define HIDN 2730
#define HID2 1365
#define HID2P 1408     // padded K for fc2
#define HIDNP 2816     // padded N for fc1 weights
#define MTOT (BB*NTOK) // 4096

// ---------------- scratch (static device globals) ---------------------------
__device__ __nv_bfloat16 g_xn_bf [MTOT*DD];
__device__ __nv_bfloat16 g_xn2_bf[MTOT*DD];
__device__ __nv_bfloat16 g_ctx_bf[MTOT*DD];
__device__ __nv_bfloat16 g_v_bf  [MTOT*DD];
__device__ __nv_bfloat16 g_wq_bf [DD*DD];
__device__ __nv_bfloat16 g_wk_bf [DD*DD];
__device__ __nv_bfloat16 g_wv_bf [DD*DD];
__device__ __nv_bfloat16 g_wo_bf [DD*DD];
__device__ __nv_bfloat16 g_fc1w_bf[(size_t)HIDNP*DD];
__device__ __nv_bfloat16 g_fc2w_bf[(size_t)DD*HID2P];
__device__ __nv_bfloat16 g_hs_bf  [(size_t)MTOT*HID2P];
__device__ float g_q   [MTOT*DD];
__device__ float g_k   [MTOT*DD];
__device__ float g_vf  [MTOT*DD];   // unused sink for mode-2 GEMM float path
__device__ float g_x1  [MTOT*DD];
__device__ float g_hpre[(size_t)MTOT*HIDN];

// ---------------- base-ISA helpers ------------------------------------------
__device__ __forceinline__ uint32_t smem_to_u32(const void* p) {
    uint32_t a;
    asm("{ .reg .u64 t; cvta.to.shared.u64 t, %1; cvt.u32.u64 %0, t; }"
        : "=r"(a) : "l"(p));
    return a;
}
#define SMEM_SWIZZLE_128B(o) ((o) ^ (((o) >> 3) & 0x70))

__device__ __forceinline__ void cp_async16(uint32_t saddr, const void* gptr) {
    asm volatile("cp.async.cg.shared.global [%0], [%1], 16;"
                 :: "r"(saddr), "l"(gptr));
}
__device__ __forceinline__ void ldmatrix_x4(uint32_t& r0, uint32_t& r1,
                                            uint32_t& r2, uint32_t& r3,
                                            uint32_t addr) {
    asm volatile("ldmatrix.sync.aligned.m8n8.x4.shared.b16 {%0,%1,%2,%3}, [%4];"
                 : "=r"(r0), "=r"(r1), "=r"(r2), "=r"(r3) : "r"(addr));
}
__device__ __forceinline__ void ldmatrix_x4_trans(uint32_t& r0, uint32_t& r1,
                                                  uint32_t& r2, uint32_t& r3,
                                                  uint32_t addr) {
    asm volatile("ldmatrix.sync.aligned.m8n8.x4.trans.shared.b16 {%0,%1,%2,%3}, [%4];"
                 : "=r"(r0), "=r"(r1), "=r"(r2), "=r"(r3) : "r"(addr));
}
__device__ __forceinline__ void mma_bf16(float* c,
                                         uint32_t a0, uint32_t a1, uint32_t a2, uint32_t a3,
                                         uint32_t b0, uint32_t b1) {
    asm volatile(
        "mma.sync.aligned.m16n8k16.row.col.f32.bf16.bf16.f32 "
        "{%0,%1,%2,%3}, {%4,%5,%6,%7}, {%8,%9}, {%0,%1,%2,%3};"
        : "+f"(c[0]), "+f"(c[1]), "+f"(c[2]), "+f"(c[3])
        : "r"(a0), "r"(a1), "r"(a2), "r"(a3), "r"(b0), "r"(b1));
}
__device__ __forceinline__ void mma_tf32(float* c,
                                         uint32_t a0, uint32_t a1, uint32_t a2, uint32_t a3,
                                         uint32_t b0, uint32_t b1) {
    asm volatile(
        "mma.sync.aligned.m16n8k8.row.col.f32.tf32.tf32.f32 "
        "{%0,%1,%2,%3}, {%4,%5,%6,%7}, {%8,%9}, {%0,%1,%2,%3};"
        : "+f"(c[0]), "+f"(c[1]), "+f"(c[2]), "+f"(c[3])
        : "r"(a0), "r"(a1), "r"(a2), "r"(a3), "r"(b0), "r"(b1));
}
__device__ __forceinline__ float ex2f(float x) {
    float r; asm("ex2.approx.f32 %0, %1;" : "=f"(r) : "f"(x)); return r;
}
__device__ __forceinline__ float sqrt_ap(float x) {
    float r; asm("sqrt.approx.f32 %0, %1;" : "=f"(r) : "f"(x)); return r;
}
__device__ __forceinline__ uint32_t cvt_tf32(float x) {
    uint32_t r; asm("cvt.rna.tf32.f32 %0, %1;" : "=r"(r) : "f"(x)); return r;
}

// ---------------- bf16 warp-MMA NT GEMM -------------------------------------
// C[M,N] = A[M,K] * Bw[N,K]^T + bias[N]    A,Bw bf16 K-major
// mode 0: C fp32 plain  mode 1: C = res + gamma*(dot+bias)  mode 2: Cb bf16
// CTA 128x64, BK=64, 8 warps (2m x 4n), double-buffered cp.async (48KB).
__global__ void __launch_bounds__(256) gemm_mma(
    const __nv_bfloat16* __restrict__ A,
    const __nv_bfloat16* __restrict__ Bw,
    const float* __restrict__ bias,
    float* __restrict__ C, __nv_bfloat16* __restrict__ Cb,
    int ldc, int Nc, int K,
    const float* __restrict__ res, const float* __restrict__ gamma, int mode)
{
    extern __shared__ char smem[];
    uint32_t sbase = smem_to_u32(smem);
    const int tid = threadIdx.x, lane = tid & 31, wid = tid >> 5;
    const int wm = wid & 1, wn = wid >> 1;
    const int bm = blockIdx.y * 128, bn = blockIdx.x * 64;

    const uint32_t STAGE = 24576u;
    const uint32_t BOFF  = 16384u;

    float acc[4][2][4];
    #pragma unroll
    for (int i = 0; i < 4; i++)
        #pragma unroll
        for (int j = 0; j < 2; j++)
            #pragma unroll
            for (int t = 0; t < 4; t++) acc[i][j][t] = 0.0f;

    const int lrow = tid >> 3;
    const int lcol = tid & 7;
    const int nch  = K >> 6;

    const int arow  = wm * 64 + (lane & 15);
    const int akoff = lane >> 4;
    const int brow  = wn * 16 + (lane & 7) + ((lane >> 4) << 3);
    const int bkoff = (lane >> 3) & 1;

    auto issue = [&](int c, int s) {
        uint32_t sb = sbase + (uint32_t)s * STAGE;
        #pragma unroll
        for (int i = 0; i < 4; i++) {
            int r = lrow + i * 32;
            uint32_t off = SMEM_SWIZZLE_128B((uint32_t)(r * 128 + lcol * 16));
            cp_async16(sb + off, A + (size_t)(bm + r) * K + c * 64 + lcol * 8);
        }
        #pragma unroll
        for (int i = 0; i < 2; i++) {
            int r = lrow + i * 32;
            uint32_t off = SMEM_SWIZZLE_128B((uint32_t)(r * 128 + lcol * 16));
            cp_async16(sb + BOFF + off, Bw + (size_t)(bn + r) * K + c * 64 + lcol * 8);
        }
        asm volatile("cp.async.commit_group;" ::: "memory");
    };

    issue(0, 0);
    for (int c = 0; c < nch; c++) {
        int s = c & 1;
        if (c + 1 < nch) {
            issue(c + 1, (c + 1) & 1);
            asm volatile("cp.async.wait_group 1;" ::: "memory");
        } else {
            asm volatile("cp.async.wait_group 0;" ::: "memory");
        }
        __syncthreads();

        uint32_t sa  = sbase + (uint32_t)s * STAGE;
        uint32_t sbb = sa + BOFF;
        #pragma unroll
        for (int ks = 0; ks < 4; ks++) {
            uint32_t a[4][4], b[4];
            #pragma unroll
            for (int mi = 0; mi < 4; mi++) {
                int r = arow + mi * 16;
                uint32_t addr = sa + SMEM_SWIZZLE_128B(
                    (uint32_t)(r * 128 + (2 * ks + akoff) * 16));
                ldmatrix_x4(a[mi][0], a[mi][1], a[mi][2], a[mi][3], addr);
            }
            {
                uint32_t addr = sbb + SMEM_SWIZZLE_128B(
                    (uint32_t)(brow * 128 + (2 * ks + bkoff) * 16));
                ldmatrix_x4(b[0], b[1], b[2], b[3], addr);
            }
            #pragma unroll
            for (int mi = 0; mi < 4; mi++) {
                mma_bf16(acc[mi][0], a[mi][0], a[mi][1], a[mi][2], a[mi][3], b[0], b[1]);
                mma_bf16(acc[mi][1], a[mi][0], a[mi][1], a[mi][2], a[mi][3], b[2], b[3]);
            }
        }
        __syncthreads();
    }

    int rbase = bm + wm * 64 + (lane >> 2);
    int cbase = bn + wn * 16 + 2 * (lane & 3);
    #pragma unroll
    for (int mi = 0; mi < 4; mi++) {
        int r0 = rbase + mi * 16;
        #pragma unroll
        for (int ni = 0; ni < 2; ni++) {
            int n0 = cbase + ni * 8;
            if (n0 < Nc) {
                float b0 = bias[n0], b1 = bias[n0 + 1];
                float v0 = acc[mi][ni][0] + b0, v1 = acc[mi][ni][1] + b1;
                float v2 = acc[mi][ni][2] + b0, v3 = acc[mi][ni][3] + b1;
                if (mode == 2) {
                    *(__nv_bfloat162*)&Cb[(size_t)r0 * ldc + n0] =
                        __floats2bfloat162_rn(v0, v1);
                    *(__nv_bfloat162*)&Cb[(size_t)(r0 + 8) * ldc + n0] =
                        __floats2bfloat162_rn(v2, v3);
                } else {
                    if (mode == 1) {
                        float g0 = gamma[n0], g1 = gamma[n0 + 1];
                        v0 = res[(size_t)r0 * ldc + n0]           + g0 * v0;
                        v1 = res[(size_t)r0 * ldc + n0 + 1]       + g1 * v1;
                        v2 = res[(size_t)(r0 + 8) * ldc + n0]     + g0 * v2;
                        v3 = res[(size_t)(r0 + 8) * ldc + n0 + 1] + g1 * v3;
                    }
                    *(float2*)&C[(size_t)r0 * ldc + n0]       = make_float2(v0, v1);
                    *(float2*)&C[(size_t)(r0 + 8) * ldc + n0] = make_float2(v2, v3);
                }
            }
        }
    }
}

// ---------------- LayerNorm -> bf16 -----------------------------------------
__global__ void ln_bf16_kernel(const float* __restrict__ x,
                               const float* __restrict__ w,
                               const float* __restrict__ b,
                               __nv_bfloat16* __restrict__ out) {
    int row = blockIdx.x;
    int t = threadIdx.x;
    const float4* xr = (const float4*)(x + (size_t)row * DD);
    float4 v = xr[t];
    float s  = v.x + v.y + v.z + v.w;
    float sq = v.x*v.x + v.y*v.y + v.z*v.z + v.w*v.w;
    #pragma unroll
    for (int o = 16; o; o >>= 1) {
        s  += __shfl_xor_sync(0xffffffffu, s,  o);
        sq += __shfl_xor_sync(0xffffffffu, sq, o);
    }
    __shared__ float ss[4], ssq[4];
    if ((t & 31) == 0) { ss[t >> 5] = s; ssq[t >> 5] = sq; }
    __syncthreads();
    s  = ss[0] + ss[1] + ss[2] + ss[3];
    sq = ssq[0] + ssq[1] + ssq[2] + ssq[3];
    float mean = s * (1.0f / DD);
    float var  = sq * (1.0f / DD) - mean * mean;
    float rstd = rsqrtf(var + 1e-5f);
    float4 wv = ((const float4*)w)[t];
    float4 bv = ((const float4*)b)[t];
    float o0 = (v.x - mean) * rstd * wv.x + bv.x;
    float o1 = (v.y - mean) * rstd * wv.y + bv.y;
    float o2 = (v.z - mean) * rstd * wv.z + bv.z;
    float o3 = (v.w - mean) * rstd * wv.w + bv.w;
    __nv_bfloat162* orow = (__nv_bfloat162*)(out + (size_t)row * DD);
    orow[t * 2]     = __floats2bfloat162_rn(o0, o1);
    orow[t * 2 + 1] = __floats2bfloat162_rn(o2, o3);
}

// ---------------- weight fp32 -> bf16 (with padding) ------------------------
__global__ void conv_w_kernel(const float* __restrict__ src, __nv_bfloat16* __restrict__ dst,
                              int N, int K, int Npad, int Kpad) {
    size_t idx = (size_t)blockIdx.x * 256 + threadIdx.x;
    size_t total = (size_t)Npad * Kpad;
    if (idx >= total) return;
    int n = (int)(idx / Kpad);
    int k = (int)(idx - (size_t)n * Kpad);
    float v = (n < N && k < K) ? src[(size_t)n * K + k] : 0.0f;
    dst[idx] = __float2bfloat16(v);
}

// ---------------- FA2 warp-MMA attention with distance-ALiBi ----------------
// grid (NTOK/64, HH, BB), 128 threads (4 warps x 16 query rows).
// QK^T in tf32 (K fp32 smem), softmax fp32, PV in bf16 (V bf16 smem, ldmatrix).
__global__ void __launch_bounds__(128) attn_mma(
    const float* __restrict__ q, const float* __restrict__ k,
    const __nv_bfloat16* __restrict__ vb, const float* __restrict__ coords,
    __nv_bfloat16* __restrict__ ctx)
{
    const int b = blockIdx.z, h = blockIdx.y, qt = blockIdx.x;
    const int tid = threadIdx.x, lane = tid & 31, wid = tid >> 5;

    __shared__ __align__(128) float Ksm[64 * 68];
    __shared__ __align__(128) __nv_bfloat16 Vsm[64 * 64];
    __shared__ float kcx[64], kcy[64];

    const float LOG2E = 1.4426950408889634f;
    const float qscale = 0.125f * LOG2E;
    const float slope2 = exp2f(-(float)(h + 1)) * LOG2E;

    const int r0 = lane >> 2;
    const int gq0 = b * NTOK + qt * 64 + wid * 16 + r0;

    uint32_t a[8][4];
    {
        const float* qp0 = q + (size_t)gq0 * DD + h * DHH;
        const float* qp1 = qp0 + 8 * DD;
        int c = lane & 3;
        #pragma unroll
        for (int kt = 0; kt < 8; kt++) {
            a[kt][0] = cvt_tf32(qp0[kt * 8 + c]     * qscale);
            a[kt][1] = cvt_tf32(qp1[kt * 8 + c]     * qscale);
            a[kt][2] = cvt_tf32(qp0[kt * 8 + c + 4] * qscale);
            a[kt][3] = cvt_tf32(qp1[kt * 8 + c + 4] * qscale);
        }
    }
    float qx0 = coords[(size_t)gq0 * 2],       qy0 = coords[(size_t)gq0 * 2 + 1];
    float qx1 = coords[(size_t)(gq0 + 8) * 2], qy1 = coords[(size_t)(gq0 + 8) * 2 + 1];

    float o[8][4];
    #pragma unroll
    for (int j = 0; j < 8; j++)
        #pragma unroll
        for (int t = 0; t < 4; t++) o[j][t] = 0.0f;
    float m0 = -1e30f, m1 = -1e30f, l0 = 0.0f, l1 = 0.0f;

    uint32_t ksm_u = smem_to_u32(Ksm);
    uint32_t vsm_u = smem_to_u32(Vsm);
    const int c0base = 2 * (lane & 3);
    const uint32_t ksm_frag = ksm_u + ((uint32_t)(lane >> 2) * 68u + (uint32_t)(lane & 3)) * 4u;

    for (int kb = 0; kb < NTOK; kb += 64) {
        __syncthreads();
        {
            int row = tid >> 1, half = tid & 1;
            const float* kg = k + (size_t)(b * NTOK + kb + row) * DD + h * DHH + half * 32;
            uint32_t ks = ksm_u + (uint32_t)(row * 68 + half * 32) * 4u;
            #pragma unroll
            for (int i = 0; i < 8; i++) cp_async16(ks + i * 16u, kg + i * 4);

            const __nv_bfloat16* vg = vb + (size_t)(b * NTOK + kb + row) * DD + h * DHH + half * 32;
            #pragma unroll
            for (int i = 0; i < 4; i++) {
                uint32_t off = SMEM_SWIZZLE_128B((uint32_t)(row * 128 + half * 64 + i * 16));
                cp_async16(vsm_u + off, vg + i * 8);
            }
            if (tid < 64) {
                float2 cc = *(const float2*)(coords + (size_t)(b * NTOK + kb + tid) * 2);
                kcx[tid] = cc.x; kcy[tid] = cc.y;
            }
        }
        asm volatile("cp.async.commit_group;" ::: "memory");
        asm volatile("cp.async.wait_group 0;" ::: "memory");
        __syncthreads();

        float sacc[8][4];
        #pragma unroll
        for (int j = 0; j < 8; j++)
            #pragma unroll
            for (int t = 0; t < 4; t++) sacc[j][t] = 0.0f;
        #pragma unroll
        for (int kt = 0; kt < 8; kt++) {
            #pragma unroll
            for (int j = 0; j < 8; j++) {
                uint32_t addr = ksm_frag + (uint32_t)(j * 8 * 68 + kt * 8) * 4u;
                uint32_t b0, b1;
                asm("ld.shared.b32 %0, [%1];" : "=r"(b0) : "r"(addr));
                asm("ld.shared.b32 %0, [%1];" : "=r"(b1) : "r"(addr + 16u));
                mma_tf32(sacc[j], a[kt][0], a[kt][1], a[kt][2], a[kt][3], b0, b1);
            }
        }

        float tm0 = -1e30f, tm1 = -1e30f;
        #pragma unroll
        for (int j = 0; j < 8; j++) {
            int c = 8 * j + c0base;
            float kx0 = kcx[c], kx1 = kcx[c + 1];
            float ky0 = kcy[c], ky1 = kcy[c + 1];
            float dxa = qx0 - kx0, dya = qy0 - ky0;
            float dxb = qx0 - kx1, dyb = qy0 - ky1;
            float dxc = qx1 - kx0, dyc = qy1 - ky0;
            float dxd = qx1 - kx1, dyd = qy1 - ky1;
            sacc[j][0] -= slope2 * sqrt_ap(dxa * dxa + dya * dya);
            sacc[j][1] -= slope2 * sqrt_ap(dxb * dxb + dyb * dyb);
            sacc[j][2] -= slope2 * sqrt_ap(dxc * dxc + dyc * dyc);
            sacc[j][3] -= slope2 * sqrt_ap(dxd * dxd + dyd * dyd);
            tm0 = fmaxf(tm0, fmaxf(sacc[j][0], sacc[j][1]));
            tm1 = fmaxf(tm1, fmaxf(sacc[j][2], sacc[j][3]));
        }
        #pragma unroll
        for (int off = 1; off <= 2; off <<= 1) {
            tm0 = fmaxf(tm0, __shfl_xor_sync(0xffffffffu, tm0, off));
            tm1 = fmaxf(tm1, __shfl_xor_sync(0xffffffffu, tm1, off));
        }

        float mn0 = fmaxf(m0, tm0), mn1 = fmaxf(m1, tm1);
        float cr0 = ex2f(m0 - mn0), cr1 = ex2f(m1 - mn1);
        m0 = mn0; m1 = mn1;
        l0 *= cr0; l1 *= cr1;
        #pragma unroll
        for (int j = 0; j < 8; j++) {
            o[j][0] *= cr0; o[j][1] *= cr0;
            o[j][2] *= cr1; o[j][3] *= cr1;
        }
        #pragma unroll
        for (int j = 0; j < 8; j++) {
            float p0 = ex2f(sacc[j][0] - m0);
            float p1 = ex2f(sacc[j][1] - m0);
            float p2 = ex2f(sacc[j][2] - m1);
            float p3 = ex2f(sacc[j][3] - m1);
            l0 += p0 + p1; l1 += p2 + p3;
            sacc[j][0] = p0; sacc[j][1] = p1; sacc[j][2] = p2; sacc[j][3] = p3;
        }

        #pragma unroll
        for (int t = 0; t < 4; t++) {
            __nv_bfloat162 h0 = __floats2bfloat162_rn(sacc[2*t][0],   sacc[2*t][1]);
            __nv_bfloat162 h1 = __floats2bfloat162_rn(sacc[2*t][2],   sacc[2*t][3]);
            __nv_bfloat162 h2 = __floats2bfloat162_rn(sacc[2*t+1][0], sacc[2*t+1][1]);
            __nv_bfloat162 h3 = __floats2bfloat162_rn(sacc[2*t+1][2], sacc[2*t+1][3]);
            uint32_t pa0 = *(uint32_t*)&h0, pa1 = *(uint32_t*)&h1;
            uint32_t pa2 = *(uint32_t*)&h2, pa3 = *(uint32_t*)&h3;
            #pragma unroll
            for (int g = 0; g < 4; g++) {
                uint32_t addr = vsm_u + SMEM_SWIZZLE_128B(
                    (uint32_t)((16 * t + (lane & 15)) * 128 + (16 * g + 8 * (lane >> 4)) * 2));
                uint32_t b0, b1, b2, b3;
                ldmatrix_x4_trans(b0, b1, b2, b3, addr);
                mma_bf16(o[2 * g],     pa0, pa1, pa2, pa3, b0, b1);
                mma_bf16(o[2 * g + 1], pa0, pa1, pa2, pa3, b2, b3);
            }
        }
    }

    #pragma unroll
    for (int off = 1; off <= 2; off <<= 1) {
        l0 += __shfl_xor_sync(0xffffffffu, l0, off);
        l1 += __shfl_xor_sync(0xffffffffu, l1, off);
    }
    float inv0 = 1.0f / l0, inv1 = 1.0f / l1;
    __nv_bfloat16* crow0 = ctx + (size_t)gq0 * DD + h * DHH;
    __nv_bfloat16* crow1 = crow0 + 8 * DD;
    #pragma unroll
    for (int j = 0; j < 8; j++) {
        int d = 8 * j + c0base;
        *(__nv_bfloat162*)(crow0 + d) = __floats2bfloat162_rn(o[j][0] * inv0, o[j][1] * inv0);
        *(__nv_bfloat162*)(crow1 + d) = __floats2bfloat162_rn(o[j][2] * inv1, o[j][3] * inv1);
    }
}

// ---------------- SwiGLU -> bf16 (padded) -----------------------------------
__global__ void swiglu_kernel(const float* __restrict__ hpre, __nv_bfloat16* __restrict__ hs) {
    size_t idx = (size_t)blockIdx.x * 256 + threadIdx.x;
    if (idx >= (size_t)MTOT * HID2P) return;
    int m = (int)(idx / HID2P);
    int j = (int)(idx - (size_t)m * HID2P);
    float val = 0.0f;
    if (j < HID2) {
        float h1 = hpre[(size_t)m * HIDN + j];
        float h2 = hpre[(size_t)m * HIDN + HID2 + j];
        float sg = 1.0f / (1.0f + __expf(-h1));
        val = h1 * sg * h2;
    }
    hs[idx] = __float2bfloat16(val);
}

// ---------------- launcher --------------------------------------------------
extern "C" void kernel_launch(void* const* d_in, const int* in_sizes, int n_in,
                              void* d_out, int out_size) {
    (void)in_sizes; (void)n_in; (void)out_size;
    const float* x      = (const float*)d_in[0];
    const float* coords = (const float*)d_in[1];
    const float* q_w    = (const float*)d_in[2];
    const float* q_b    = (const float*)d_in[3];
    const float* k_w    = (const float*)d_in[4];
    const float* k_b    = (const float*)d_in[5];
    const float* v_w    = (const float*)d_in[6];
    const float* v_b    = (const float*)d_in[7];
    const float* o_w    = (const float*)d_in[8];
    const float* o_b    = (const float*)d_in[9];
    const float* gamma1 = (const float*)d_in[10];
    const float* ln1_w  = (const float*)d_in[11];
    const float* ln1_b  = (const float*)d_in[12];
    const float* fc1_w  = (const float*)d_in[13];
    const float* fc1_b  = (const float*)d_in[14];
    const float* fc2_w  = (const float*)d_in[15];
    const float* fc2_b  = (const float*)d_in[16];
    const float* gamma2 = (const float*)d_in[17];
    const float* ln2_w  = (const float*)d_in[18];
    const float* ln2_b  = (const float*)d_in[19];
    float* out = (float*)d_out;

    __nv_bfloat16 *xn, *xn2, *ctxb, *vbf, *wq, *wk, *wv, *wo, *fc1w, *fc2w, *hsb;
    float *q, *k, *vf, *x1, *hpre;
    cudaGetSymbolAddress((void**)&xn,   g_xn_bf);
    cudaGetSymbolAddress((void**)&xn2,  g_xn2_bf);
    cudaGetSymbolAddress((void**)&ctxb, g_ctx_bf);
    cudaGetSymbolAddress((void**)&vbf,  g_v_bf);
    cudaGetSymbolAddress((void**)&wq,   g_wq_bf);
    cudaGetSymbolAddress((void**)&wk,   g_wk_bf);
    cudaGetSymbolAddress((void**)&wv,   g_wv_bf);
    cudaGetSymbolAddress((void**)&wo,   g_wo_bf);
    cudaGetSymbolAddress((void**)&fc1w, g_fc1w_bf);
    cudaGetSymbolAddress((void**)&fc2w, g_fc2w_bf);
    cudaGetSymbolAddress((void**)&hsb,  g_hs_bf);
    cudaGetSymbolAddress((void**)&q,    g_q);
    cudaGetSymbolAddress((void**)&k,    g_k);
    cudaGetSymbolAddress((void**)&vf,   g_vf);
    cudaGetSymbolAddress((void**)&x1,   g_x1);
    cudaGetSymbolAddress((void**)&hpre, g_hpre);

    const int SMEM_GEMM = 49152;

    {
        int n1 = DD * DD;
        conv_w_kernel<<<(n1 + 255) / 256, 256>>>(q_w, wq, DD, DD, DD, DD);
        conv_w_kernel<<<(n1 + 255) / 256, 256>>>(k_w, wk, DD, DD, DD, DD);
        conv_w_kernel<<<(n1 + 255) / 256, 256>>>(v_w, wv, DD, DD, DD, DD);
        conv_w_kernel<<<(n1 + 255) / 256, 256>>>(o_w, wo, DD, DD, DD, DD);
        size_t n2 = (size_t)HIDNP * DD;
        conv_w_kernel<<<(int)((n2 + 255) / 256), 256>>>(fc1_w, fc1w, HIDN, DD, HIDNP, DD);
        size_t n3 = (size_t)DD * HID2P;
        conv_w_kernel<<<(int)((n3 + 255) / 256), 256>>>(fc2_w, fc2w, DD, HID2, DD, HID2P);
    }

    ln_bf16_kernel<<<MTOT, 128>>>(x, ln1_w, ln1_b, xn);

    dim3 gproj(DD / 64, MTOT / 128);
    gemm_mma<<<gproj, 256, SMEM_GEMM>>>(xn, wq, q_b, q, nullptr, DD, DD, DD, nullptr, nullptr, 0);
    gemm_mma<<<gproj, 256, SMEM_GEMM>>>(xn, wk, k_b, k, nullptr, DD, DD, DD, nullptr, nullptr, 0);
    gemm_mma<<<gproj, 256, SMEM_GEMM>>>(xn, wv, v_b, vf, vbf, DD, DD, DD, nullptr, nullptr, 2);

    dim3 gattn(NTOK / 64, HH, BB);
    attn_mma<<<gattn, 128>>>(q, k, vbf, coords, ctxb);

    gemm_mma<<<gproj, 256, SMEM_GEMM>>>(ctxb, wo, o_b, x1, nullptr, DD, DD, DD, x, gamma1, 1);

    ln_bf16_kernel<<<MTOT, 128>>>(x1, ln2_w, ln2_b, xn2);

    dim3 gfc1(HIDNP / 64, MTOT / 128);
    gemm_mma<<<gfc1, 256, SMEM_GEMM>>>(xn2, fc1w, fc1_b, hpre, nullptr, HIDN, HIDN, DD, nullptr, nullptr, 0);

    size_t nsw = (size_t)MTOT * HID2P;
    swiglu_kernel<<<(int)((nsw + 255) / 256), 256>>>(hpre, hsb);

    gemm_mma<<<gproj, 256, SMEM_GEMM>>>(hsb, fc2w, fc2_b, out, nullptr, DD, DD, HID2P, x1, gamma2, 1);
}

// round 8
// speedup vs baseline: 6.6754x; 1.2408x over previous
#include <cuda_runtime.h>
#include <cuda_bf16.h>
#include <cstdint>
#include <math.h>

#define BB 2
#define NTOK 2048
#define DD 512
#define HH 8
#define DHH 64
#define HIDN 2730
#define HID2 1365
#define HID2P 1408     // padded K for fc2
#define HIDNP 2816     // padded N for fc1 weights
#define MTOT (BB*NTOK) // 4096

// ---------------- scratch (static device globals) ---------------------------
__device__ __nv_bfloat16 g_xn_bf [MTOT*DD];
__device__ __nv_bfloat16 g_xn2_bf[MTOT*DD];
__device__ __nv_bfloat16 g_ctx_bf[MTOT*DD];
__device__ __nv_bfloat16 g_q_bf  [MTOT*DD];
__device__ __nv_bfloat16 g_k_bf  [MTOT*DD];
__device__ __nv_bfloat16 g_v_bf  [MTOT*DD];
__device__ __nv_bfloat16 g_wq_bf [DD*DD];
__device__ __nv_bfloat16 g_wk_bf [DD*DD];
__device__ __nv_bfloat16 g_wv_bf [DD*DD];
__device__ __nv_bfloat16 g_wo_bf [DD*DD];
__device__ __nv_bfloat16 g_fc1w_bf[(size_t)HIDNP*DD];
__device__ __nv_bfloat16 g_fc2w_bf[(size_t)DD*HID2P];
__device__ __nv_bfloat16 g_hs_bf  [(size_t)MTOT*HID2P];
__device__ float g_x1  [MTOT*DD];
__device__ float g_hpre[(size_t)MTOT*HIDN];

// ---------------- base-ISA helpers ------------------------------------------
__device__ __forceinline__ uint32_t smem_to_u32(const void* p) {
    uint32_t a;
    asm("{ .reg .u64 t; cvta.to.shared.u64 t, %1; cvt.u32.u64 %0, t; }"
        : "=r"(a) : "l"(p));
    return a;
}
#define SMEM_SWIZZLE_128B(o) ((o) ^ (((o) >> 3) & 0x70))

__device__ __forceinline__ void cp_async16(uint32_t saddr, const void* gptr) {
    asm volatile("cp.async.cg.shared.global [%0], [%1], 16;"
                 :: "r"(saddr), "l"(gptr));
}
__device__ __forceinline__ void ldmatrix_x4(uint32_t& r0, uint32_t& r1,
                                            uint32_t& r2, uint32_t& r3,
                                            uint32_t addr) {
    asm volatile("ldmatrix.sync.aligned.m8n8.x4.shared.b16 {%0,%1,%2,%3}, [%4];"
                 : "=r"(r0), "=r"(r1), "=r"(r2), "=r"(r3) : "r"(addr));
}
__device__ __forceinline__ void ldmatrix_x4_trans(uint32_t& r0, uint32_t& r1,
                                                  uint32_t& r2, uint32_t& r3,
                                                  uint32_t addr) {
    asm volatile("ldmatrix.sync.aligned.m8n8.x4.trans.shared.b16 {%0,%1,%2,%3}, [%4];"
                 : "=r"(r0), "=r"(r1), "=r"(r2), "=r"(r3) : "r"(addr));
}
__device__ __forceinline__ void mma_bf16(float* c,
                                         uint32_t a0, uint32_t a1, uint32_t a2, uint32_t a3,
                                         uint32_t b0, uint32_t b1) {
    asm volatile(
        "mma.sync.aligned.m16n8k16.row.col.f32.bf16.bf16.f32 "
        "{%0,%1,%2,%3}, {%4,%5,%6,%7}, {%8,%9}, {%0,%1,%2,%3};"
        : "+f"(c[0]), "+f"(c[1]), "+f"(c[2]), "+f"(c[3])
        : "r"(a0), "r"(a1), "r"(a2), "r"(a3), "r"(b0), "r"(b1));
}
__device__ __forceinline__ float ex2f(float x) {
    float r; asm("ex2.approx.f32 %0, %1;" : "=f"(r) : "f"(x)); return r;
}
__device__ __forceinline__ float sqrt_ap(float x) {
    float r; asm("sqrt.approx.f32 %0, %1;" : "=f"(r) : "f"(x)); return r;
}

// ---------------- bf16 warp-MMA NT GEMM -------------------------------------
// C[M,N] = A[M,K] * Bw[N,K]^T + bias[N]    A,Bw bf16 K-major
// mode 0: C fp32 plain  mode 1: C = res + gamma*(dot+bias)  mode 2: Cb bf16
// CTA 128x64, BK=64, 8 warps (2m x 4n), double-buffered cp.async (48KB).
__global__ void __launch_bounds__(256) gemm_mma(
    const __nv_bfloat16* __restrict__ A,
    const __nv_bfloat16* __restrict__ Bw,
    const float* __restrict__ bias,
    float* __restrict__ C, __nv_bfloat16* __restrict__ Cb,
    int ldc, int Nc, int K,
    const float* __restrict__ res, const float* __restrict__ gamma, int mode)
{
    extern __shared__ char smem[];
    uint32_t sbase = smem_to_u32(smem);
    const int tid = threadIdx.x, lane = tid & 31, wid = tid >> 5;
    const int wm = wid & 1, wn = wid >> 1;
    const int bm = blockIdx.y * 128, bn = blockIdx.x * 64;

    const uint32_t STAGE = 24576u;
    const uint32_t BOFF  = 16384u;

    float acc[4][2][4];
    #pragma unroll
    for (int i = 0; i < 4; i++)
        #pragma unroll
        for (int j = 0; j < 2; j++)
            #pragma unroll
            for (int t = 0; t < 4; t++) acc[i][j][t] = 0.0f;

    const int lrow = tid >> 3;
    const int lcol = tid & 7;
    const int nch  = K >> 6;

    const int arow  = wm * 64 + (lane & 15);
    const int akoff = lane >> 4;
    const int brow  = wn * 16 + (lane & 7) + ((lane >> 4) << 3);
    const int bkoff = (lane >> 3) & 1;

    auto issue = [&](int c, int s) {
        uint32_t sb = sbase + (uint32_t)s * STAGE;
        #pragma unroll
        for (int i = 0; i < 4; i++) {
            int r = lrow + i * 32;
            uint32_t off = SMEM_SWIZZLE_128B((uint32_t)(r * 128 + lcol * 16));
            cp_async16(sb + off, A + (size_t)(bm + r) * K + c * 64 + lcol * 8);
        }
        #pragma unroll
        for (int i = 0; i < 2; i++) {
            int r = lrow + i * 32;
            uint32_t off = SMEM_SWIZZLE_128B((uint32_t)(r * 128 + lcol * 16));
            cp_async16(sb + BOFF + off, Bw + (size_t)(bn + r) * K + c * 64 + lcol * 8);
        }
        asm volatile("cp.async.commit_group;" ::: "memory");
    };

    issue(0, 0);
    for (int c = 0; c < nch; c++) {
        int s = c & 1;
        if (c + 1 < nch) {
            issue(c + 1, (c + 1) & 1);
            asm volatile("cp.async.wait_group 1;" ::: "memory");
        } else {
            asm volatile("cp.async.wait_group 0;" ::: "memory");
        }
        __syncthreads();

        uint32_t sa  = sbase + (uint32_t)s * STAGE;
        uint32_t sbb = sa + BOFF;
        #pragma unroll
        for (int ks = 0; ks < 4; ks++) {
            uint32_t a[4][4], b[4];
            #pragma unroll
            for (int mi = 0; mi < 4; mi++) {
                int r = arow + mi * 16;
                uint32_t addr = sa + SMEM_SWIZZLE_128B(
                    (uint32_t)(r * 128 + (2 * ks + akoff) * 16));
                ldmatrix_x4(a[mi][0], a[mi][1], a[mi][2], a[mi][3], addr);
            }
            {
                uint32_t addr = sbb + SMEM_SWIZZLE_128B(
                    (uint32_t)(brow * 128 + (2 * ks + bkoff) * 16));
                ldmatrix_x4(b[0], b[1], b[2], b[3], addr);
            }
            #pragma unroll
            for (int mi = 0; mi < 4; mi++) {
                mma_bf16(acc[mi][0], a[mi][0], a[mi][1], a[mi][2], a[mi][3], b[0], b[1]);
                mma_bf16(acc[mi][1], a[mi][0], a[mi][1], a[mi][2], a[mi][3], b[2], b[3]);
            }
        }
        __syncthreads();
    }

    int rbase = bm + wm * 64 + (lane >> 2);
    int cbase = bn + wn * 16 + 2 * (lane & 3);
    #pragma unroll
    for (int mi = 0; mi < 4; mi++) {
        int r0 = rbase + mi * 16;
        #pragma unroll
        for (int ni = 0; ni < 2; ni++) {
            int n0 = cbase + ni * 8;
            if (n0 < Nc) {
                float b0 = bias[n0], b1 = bias[n0 + 1];
                float v0 = acc[mi][ni][0] + b0, v1 = acc[mi][ni][1] + b1;
                float v2 = acc[mi][ni][2] + b0, v3 = acc[mi][ni][3] + b1;
                if (mode == 2) {
                    *(__nv_bfloat162*)&Cb[(size_t)r0 * ldc + n0] =
                        __floats2bfloat162_rn(v0, v1);
                    *(__nv_bfloat162*)&Cb[(size_t)(r0 + 8) * ldc + n0] =
                        __floats2bfloat162_rn(v2, v3);
                } else {
                    if (mode == 1) {
                        float g0 = gamma[n0], g1 = gamma[n0 + 1];
                        v0 = res[(size_t)r0 * ldc + n0]           + g0 * v0;
                        v1 = res[(size_t)r0 * ldc + n0 + 1]       + g1 * v1;
                        v2 = res[(size_t)(r0 + 8) * ldc + n0]     + g0 * v2;
                        v3 = res[(size_t)(r0 + 8) * ldc + n0 + 1] + g1 * v3;
                    }
                    *(float2*)&C[(size_t)r0 * ldc + n0]       = make_float2(v0, v1);
                    *(float2*)&C[(size_t)(r0 + 8) * ldc + n0] = make_float2(v2, v3);
                }
            }
        }
    }
}

// ---------------- LayerNorm -> bf16 -----------------------------------------
__global__ void ln_bf16_kernel(const float* __restrict__ x,
                               const float* __restrict__ w,
                               const float* __restrict__ b,
                               __nv_bfloat16* __restrict__ out) {
    int row = blockIdx.x;
    int t = threadIdx.x;
    const float4* xr = (const float4*)(x + (size_t)row * DD);
    float4 v = xr[t];
    float s  = v.x + v.y + v.z + v.w;
    float sq = v.x*v.x + v.y*v.y + v.z*v.z + v.w*v.w;
    #pragma unroll
    for (int o = 16; o; o >>= 1) {
        s  += __shfl_xor_sync(0xffffffffu, s,  o);
        sq += __shfl_xor_sync(0xffffffffu, sq, o);
    }
    __shared__ float ss[4], ssq[4];
    if ((t & 31) == 0) { ss[t >> 5] = s; ssq[t >> 5] = sq; }
    __syncthreads();
    s  = ss[0] + ss[1] + ss[2] + ss[3];
    sq = ssq[0] + ssq[1] + ssq[2] + ssq[3];
    float mean = s * (1.0f / DD);
    float var  = sq * (1.0f / DD) - mean * mean;
    float rstd = rsqrtf(var + 1e-5f);
    float4 wv = ((const float4*)w)[t];
    float4 bv = ((const float4*)b)[t];
    float o0 = (v.x - mean) * rstd * wv.x + bv.x;
    float o1 = (v.y - mean) * rstd * wv.y + bv.y;
    float o2 = (v.z - mean) * rstd * wv.z + bv.z;
    float o3 = (v.w - mean) * rstd * wv.w + bv.w;
    __nv_bfloat162* orow = (__nv_bfloat162*)(out + (size_t)row * DD);
    orow[t * 2]     = __floats2bfloat162_rn(o0, o1);
    orow[t * 2 + 1] = __floats2bfloat162_rn(o2, o3);
}

// ---------------- weight converts -------------------------------------------
__global__ void conv_w4_kernel(const float* __restrict__ s0, const float* __restrict__ s1,
                               const float* __restrict__ s2, const float* __restrict__ s3,
                               __nv_bfloat16* __restrict__ d0, __nv_bfloat16* __restrict__ d1,
                               __nv_bfloat16* __restrict__ d2, __nv_bfloat16* __restrict__ d3) {
    int idx = blockIdx.x * 256 + threadIdx.x;
    if (idx >= DD * DD) return;
    d0[idx] = __float2bfloat16(s0[idx]);
    d1[idx] = __float2bfloat16(s1[idx]);
    d2[idx] = __float2bfloat16(s2[idx]);
    d3[idx] = __float2bfloat16(s3[idx]);
}
__global__ void conv_w_kernel(const float* __restrict__ src, __nv_bfloat16* __restrict__ dst,
                              int N, int K, int Npad, int Kpad) {
    size_t idx = (size_t)blockIdx.x * 256 + threadIdx.x;
    size_t total = (size_t)Npad * Kpad;
    if (idx >= total) return;
    int n = (int)(idx / Kpad);
    int k = (int)(idx - (size_t)n * Kpad);
    float v = (n < N && k < K) ? src[(size_t)n * K + k] : 0.0f;
    dst[idx] = __float2bfloat16(v);
}

// ---------------- FA2 warp-MMA attention (all-bf16, double-buffered) --------
// grid (NTOK/64, HH, BB), 128 threads (4 warps x 16 query rows).
__global__ void __launch_bounds__(128) attn_mma(
    const __nv_bfloat16* __restrict__ q, const __nv_bfloat16* __restrict__ k,
    const __nv_bfloat16* __restrict__ vb, const float* __restrict__ coords,
    __nv_bfloat16* __restrict__ ctx)
{
    const int b = blockIdx.z, h = blockIdx.y, qt = blockIdx.x;
    const int tid = threadIdx.x, lane = tid & 31, wid = tid >> 5;

    __shared__ __align__(128) __nv_bfloat16 Ksm[2][64 * 64];
    __shared__ __align__(128) __nv_bfloat16 Vsm[2][64 * 64];
    __shared__ __align__(16) float2 Kc[2][64];

    const float LOG2E = 1.4426950408889634f;
    const float qscale = 0.125f * LOG2E;
    const float slope2 = exp2f(-(float)(h + 1)) * LOG2E;

    const int r0 = lane >> 2;
    const int gq0 = b * NTOK + qt * 64 + wid * 16 + r0;
    const int c0base = 2 * (lane & 3);

    // Q A-fragments direct from gmem (pairs are contiguous bf16)
    uint32_t a[4][4];
    {
        const __nv_bfloat16* qp0 = q + (size_t)gq0 * DD + h * DHH;
        const __nv_bfloat16* qp1 = qp0 + 8 * DD;
        #pragma unroll
        for (int kt = 0; kt < 4; kt++) {
            a[kt][0] = *(const uint32_t*)(qp0 + kt * 16 + c0base);
            a[kt][1] = *(const uint32_t*)(qp1 + kt * 16 + c0base);
            a[kt][2] = *(const uint32_t*)(qp0 + kt * 16 + c0base + 8);
            a[kt][3] = *(const uint32_t*)(qp1 + kt * 16 + c0base + 8);
        }
    }
    float qx0 = coords[(size_t)gq0 * 2],       qy0 = coords[(size_t)gq0 * 2 + 1];
    float qx1 = coords[(size_t)(gq0 + 8) * 2], qy1 = coords[(size_t)(gq0 + 8) * 2 + 1];

    float o[8][4];
    #pragma unroll
    for (int j = 0; j < 8; j++)
        #pragma unroll
        for (int t = 0; t < 4; t++) o[j][t] = 0.0f;
    float m0 = -1e30f, m1 = -1e30f, l0 = 0.0f, l1 = 0.0f;

    uint32_t ksm_u = smem_to_u32(Ksm);
    uint32_t vsm_u = smem_to_u32(Vsm);
    uint32_t kc_u  = smem_to_u32(Kc);

    const int lr = tid >> 1, lh = tid & 1;
    const int brow = (lane & 7) + ((lane >> 4) << 3);
    const int bkoff = (lane >> 3) & 1;

    auto issue = [&](int kb, int s) {
        const __nv_bfloat16* kg = k  + (size_t)(b * NTOK + kb + lr) * DD + h * DHH + lh * 32;
        const __nv_bfloat16* vg = vb + (size_t)(b * NTOK + kb + lr) * DD + h * DHH + lh * 32;
        #pragma unroll
        for (int i = 0; i < 2; i++) {
            uint32_t off = SMEM_SWIZZLE_128B((uint32_t)(lr * 128 + lh * 64 + i * 32));
            cp_async16(ksm_u + (uint32_t)s * 8192u + off, kg + i * 16);
            cp_async16(ksm_u + (uint32_t)s * 8192u +
                       SMEM_SWIZZLE_128B((uint32_t)(lr * 128 + lh * 64 + i * 32 + 16)), kg + i * 16 + 8);
            cp_async16(vsm_u + (uint32_t)s * 8192u + off, vg + i * 16);
            cp_async16(vsm_u + (uint32_t)s * 8192u +
                       SMEM_SWIZZLE_128B((uint32_t)(lr * 128 + lh * 64 + i * 32 + 16)), vg + i * 16 + 8);
        }
        if (tid < 32) {
            cp_async16(kc_u + (uint32_t)s * 512u + (uint32_t)tid * 16u,
                       coords + (size_t)(b * NTOK + kb) * 2 + tid * 4);
        }
        asm volatile("cp.async.commit_group;" ::: "memory");
    };

    issue(0, 0);
    const int ntiles = NTOK / 64;
    for (int c = 0; c < ntiles; c++) {
        int s = c & 1;
        if (c + 1 < ntiles) {
            issue((c + 1) * 64, s ^ 1);
            asm volatile("cp.async.wait_group 1;" ::: "memory");
        } else {
            asm volatile("cp.async.wait_group 0;" ::: "memory");
        }
        __syncthreads();

        // ---- S = Q K^T (bf16)
        float sacc[8][4];
        #pragma unroll
        for (int j = 0; j < 8; j++)
            #pragma unroll
            for (int t = 0; t < 4; t++) sacc[j][t] = 0.0f;
        uint32_t kbase = ksm_u + (uint32_t)s * 8192u;
        #pragma unroll
        for (int ks = 0; ks < 4; ks++) {
            #pragma unroll
            for (int jj = 0; jj < 4; jj++) {
                uint32_t addr = kbase + SMEM_SWIZZLE_128B(
                    (uint32_t)((jj * 16 + brow) * 128 + (2 * ks + bkoff) * 16));
                uint32_t b0, b1, b2, b3;
                ldmatrix_x4(b0, b1, b2, b3, addr);
                mma_bf16(sacc[2 * jj],     a[ks][0], a[ks][1], a[ks][2], a[ks][3], b0, b1);
                mma_bf16(sacc[2 * jj + 1], a[ks][0], a[ks][1], a[ks][2], a[ks][3], b2, b3);
            }
        }

        // ---- scale + distance-ALiBi + tile max
        float tm0 = -1e30f, tm1 = -1e30f;
        #pragma unroll
        for (int j = 0; j < 8; j++) {
            int cc = 8 * j + c0base;
            float2 k0 = Kc[s][cc], k1 = Kc[s][cc + 1];
            float dxa = qx0 - k0.x, dya = qy0 - k0.y;
            float dxb = qx0 - k1.x, dyb = qy0 - k1.y;
            float dxc = qx1 - k0.x, dyc = qy1 - k0.y;
            float dxd = qx1 - k1.x, dyd = qy1 - k1.y;
            sacc[j][0] = fmaf(sacc[j][0], qscale, -slope2 * sqrt_ap(dxa * dxa + dya * dya));
            sacc[j][1] = fmaf(sacc[j][1], qscale, -slope2 * sqrt_ap(dxb * dxb + dyb * dyb));
            sacc[j][2] = fmaf(sacc[j][2], qscale, -slope2 * sqrt_ap(dxc * dxc + dyc * dyc));
            sacc[j][3] = fmaf(sacc[j][3], qscale, -slope2 * sqrt_ap(dxd * dxd + dyd * dyd));
            tm0 = fmaxf(tm0, fmaxf(sacc[j][0], sacc[j][1]));
            tm1 = fmaxf(tm1, fmaxf(sacc[j][2], sacc[j][3]));
        }
        #pragma unroll
        for (int off = 1; off <= 2; off <<= 1) {
            tm0 = fmaxf(tm0, __shfl_xor_sync(0xffffffffu, tm0, off));
            tm1 = fmaxf(tm1, __shfl_xor_sync(0xffffffffu, tm1, off));
        }

        // ---- online softmax
        float mn0 = fmaxf(m0, tm0), mn1 = fmaxf(m1, tm1);
        float cr0 = ex2f(m0 - mn0), cr1 = ex2f(m1 - mn1);
        m0 = mn0; m1 = mn1;
        l0 *= cr0; l1 *= cr1;
        #pragma unroll
        for (int j = 0; j < 8; j++) {
            o[j][0] *= cr0; o[j][1] *= cr0;
            o[j][2] *= cr1; o[j][3] *= cr1;
        }
        #pragma unroll
        for (int j = 0; j < 8; j++) {
            float p0 = ex2f(sacc[j][0] - m0);
            float p1 = ex2f(sacc[j][1] - m0);
            float p2 = ex2f(sacc[j][2] - m1);
            float p3 = ex2f(sacc[j][3] - m1);
            l0 += p0 + p1; l1 += p2 + p3;
            sacc[j][0] = p0; sacc[j][1] = p1; sacc[j][2] = p2; sacc[j][3] = p3;
        }

        // ---- O += P V (bf16)
        uint32_t vbase = vsm_u + (uint32_t)s * 8192u;
        #pragma unroll
        for (int t = 0; t < 4; t++) {
            __nv_bfloat162 h0 = __floats2bfloat162_rn(sacc[2*t][0],   sacc[2*t][1]);
            __nv_bfloat162 h1 = __floats2bfloat162_rn(sacc[2*t][2],   sacc[2*t][3]);
            __nv_bfloat162 h2 = __floats2bfloat162_rn(sacc[2*t+1][0], sacc[2*t+1][1]);
            __nv_bfloat162 h3 = __floats2bfloat162_rn(sacc[2*t+1][2], sacc[2*t+1][3]);
            uint32_t pa0 = *(uint32_t*)&h0, pa1 = *(uint32_t*)&h1;
            uint32_t pa2 = *(uint32_t*)&h2, pa3 = *(uint32_t*)&h3;
            #pragma unroll
            for (int g = 0; g < 4; g++) {
                uint32_t addr = vbase + SMEM_SWIZZLE_128B(
                    (uint32_t)((16 * t + (lane & 15)) * 128 + (16 * g + 8 * (lane >> 4)) * 2));
                uint32_t b0, b1, b2, b3;
                ldmatrix_x4_trans(b0, b1, b2, b3, addr);
                mma_bf16(o[2 * g],     pa0, pa1, pa2, pa3, b0, b1);
                mma_bf16(o[2 * g + 1], pa0, pa1, pa2, pa3, b2, b3);
            }
        }
        __syncthreads();
    }

    #pragma unroll
    for (int off = 1; off <= 2; off <<= 1) {
        l0 += __shfl_xor_sync(0xffffffffu, l0, off);
        l1 += __shfl_xor_sync(0xffffffffu, l1, off);
    }
    float inv0 = 1.0f / l0, inv1 = 1.0f / l1;
    __nv_bfloat16* crow0 = ctx + (size_t)gq0 * DD + h * DHH;
    __nv_bfloat16* crow1 = crow0 + 8 * DD;
    #pragma unroll
    for (int j = 0; j < 8; j++) {
        int d = 8 * j + c0base;
        *(__nv_bfloat162*)(crow0 + d) = __floats2bfloat162_rn(o[j][0] * inv0, o[j][1] * inv0);
        *(__nv_bfloat162*)(crow1 + d) = __floats2bfloat162_rn(o[j][2] * inv1, o[j][3] * inv1);
    }
}

// ---------------- SwiGLU -> bf16 (padded) -----------------------------------
__global__ void swiglu_kernel(const float* __restrict__ hpre, __nv_bfloat16* __restrict__ hs) {
    size_t idx = (size_t)blockIdx.x * 256 + threadIdx.x;
    if (idx >= (size_t)MTOT * HID2P) return;
    int m = (int)(idx / HID2P);
    int j = (int)(idx - (size_t)m * HID2P);
    float val = 0.0f;
    if (j < HID2) {
        float h1 = hpre[(size_t)m * HIDN + j];
        float h2 = hpre[(size_t)m * HIDN + HID2 + j];
        float sg = 1.0f / (1.0f + __expf(-h1));
        val = h1 * sg * h2;
    }
    hs[idx] = __float2bfloat16(val);
}

// ---------------- launcher --------------------------------------------------
extern "C" void kernel_launch(void* const* d_in, const int* in_sizes, int n_in,
                              void* d_out, int out_size) {
    (void)in_sizes; (void)n_in; (void)out_size;
    const float* x      = (const float*)d_in[0];
    const float* coords = (const float*)d_in[1];
    const float* q_w    = (const float*)d_in[2];
    const float* q_b    = (const float*)d_in[3];
    const float* k_w    = (const float*)d_in[4];
    const float* k_b    = (const float*)d_in[5];
    const float* v_w    = (const float*)d_in[6];
    const float* v_b    = (const float*)d_in[7];
    const float* o_w    = (const float*)d_in[8];
    const float* o_b    = (const float*)d_in[9];
    const float* gamma1 = (const float*)d_in[10];
    const float* ln1_w  = (const float*)d_in[11];
    const float* ln1_b  = (const float*)d_in[12];
    const float* fc1_w  = (const float*)d_in[13];
    const float* fc1_b  = (const float*)d_in[14];
    const float* fc2_w  = (const float*)d_in[15];
    const float* fc2_b  = (const float*)d_in[16];
    const float* gamma2 = (const float*)d_in[17];
    const float* ln2_w  = (const float*)d_in[18];
    const float* ln2_b  = (const float*)d_in[19];
    float* out = (float*)d_out;

    __nv_bfloat16 *xn, *xn2, *ctxb, *qbf, *kbf, *vbf, *wq, *wk, *wv, *wo, *fc1w, *fc2w, *hsb;
    float *x1, *hpre;
    cudaGetSymbolAddress((void**)&xn,   g_xn_bf);
    cudaGetSymbolAddress((void**)&xn2,  g_xn2_bf);
    cudaGetSymbolAddress((void**)&ctxb, g_ctx_bf);
    cudaGetSymbolAddress((void**)&qbf,  g_q_bf);
    cudaGetSymbolAddress((void**)&kbf,  g_k_bf);
    cudaGetSymbolAddress((void**)&vbf,  g_v_bf);
    cudaGetSymbolAddress((void**)&wq,   g_wq_bf);
    cudaGetSymbolAddress((void**)&wk,   g_wk_bf);
    cudaGetSymbolAddress((void**)&wv,   g_wv_bf);
    cudaGetSymbolAddress((void**)&wo,   g_wo_bf);
    cudaGetSymbolAddress((void**)&fc1w, g_fc1w_bf);
    cudaGetSymbolAddress((void**)&fc2w, g_fc2w_bf);
    cudaGetSymbolAddress((void**)&hsb,  g_hs_bf);
    cudaGetSymbolAddress((void**)&x1,   g_x1);
    cudaGetSymbolAddress((void**)&hpre, g_hpre);

    const int SMEM_GEMM = 49152;

    // weight conversions
    conv_w4_kernel<<<(DD * DD + 255) / 256, 256>>>(q_w, k_w, v_w, o_w, wq, wk, wv, wo);
    {
        size_t n2 = (size_t)HIDNP * DD;
        conv_w_kernel<<<(int)((n2 + 255) / 256), 256>>>(fc1_w, fc1w, HIDN, DD, HIDNP, DD);
        size_t n3 = (size_t)DD * HID2P;
        conv_w_kernel<<<(int)((n3 + 255) / 256), 256>>>(fc2_w, fc2w, DD, HID2, DD, HID2P);
    }

    ln_bf16_kernel<<<MTOT, 128>>>(x, ln1_w, ln1_b, xn);

    // QKV projections (bf16 outputs for attention)
    dim3 gproj(DD / 64, MTOT / 128);
    gemm_mma<<<gproj, 256, SMEM_GEMM>>>(xn, wq, q_b, nullptr, qbf, DD, DD, DD, nullptr, nullptr, 2);
    gemm_mma<<<gproj, 256, SMEM_GEMM>>>(xn, wk, k_b, nullptr, kbf, DD, DD, DD, nullptr, nullptr, 2);
    gemm_mma<<<gproj, 256, SMEM_GEMM>>>(xn, wv, v_b, nullptr, vbf, DD, DD, DD, nullptr, nullptr, 2);

    // FA2 attention (all bf16, double-buffered)
    dim3 gattn(NTOK / 64, HH, BB);
    attn_mma<<<gattn, 128>>>(qbf, kbf, vbf, coords, ctxb);

    // O projection + residual1
    gemm_mma<<<gproj, 256, SMEM_GEMM>>>(ctxb, wo, o_b, x1, nullptr, DD, DD, DD, x, gamma1, 1);

    ln_bf16_kernel<<<MTOT, 128>>>(x1, ln2_w, ln2_b, xn2);

    // fc1
    dim3 gfc1(HIDNP / 64, MTOT / 128);
    gemm_mma<<<gfc1, 256, SMEM_GEMM>>>(xn2, fc1w, fc1_b, hpre, nullptr, HIDN, HIDN, DD, nullptr, nullptr, 0);

    // SwiGLU -> bf16 padded
    size_t nsw = (size_t)MTOT * HID2P;
    swiglu_kernel<<<(int)((nsw + 255) / 256), 256>>>(hpre, hsb);

    // fc2 + residual2 -> out
    gemm_mma<<<gproj, 256, SMEM_GEMM>>>(hsb, fc2w, fc2_b, out, nullptr, DD, DD, HID2P, x1, gamma2, 1);
}

// round 9
// speedup vs baseline: 7.1581x; 1.0723x over previous
#include <cuda_runtime.h>
#include <cuda_bf16.h>
#include <cstdint>
#include <math.h>

#define BB 2
#define NTOK 2048
#define DD 512
#define HH 8
#define DHH 64
#define HIDN 2730
#define HID2 1365
#define HID2P 1408     // padded (interleaved/2) width of hs
#define HIDNP 2816     // padded interleaved N for fc1
#define MTOT (BB*NTOK) // 4096
#define QKVN 1536

// ---------------- scratch (static device globals) ---------------------------
__device__ __nv_bfloat16 g_xn_bf [MTOT*DD];
__device__ __nv_bfloat16 g_xn2_bf[MTOT*DD];
__device__ __nv_bfloat16 g_ctx_bf[MTOT*DD];
__device__ __nv_bfloat16 g_qkv_bf[3*MTOT*DD];
__device__ __nv_bfloat16 g_wqkv_bf[QKVN*DD];
__device__ float         g_qkvb  [QKVN];
__device__ __nv_bfloat16 g_wo_bf [DD*DD];
__device__ __nv_bfloat16 g_fc1w_bf[(size_t)HIDNP*DD];   // interleaved h1/h2 rows
__device__ float         g_fc1b  [HIDNP];               // interleaved bias
__device__ __nv_bfloat16 g_fc2w_bf[(size_t)DD*HID2P];
__device__ __nv_bfloat16 g_hs_bf  [(size_t)MTOT*HID2P];
__device__ float g_x1  [MTOT*DD];

// ---------------- base-ISA helpers ------------------------------------------
__device__ __forceinline__ uint32_t smem_to_u32(const void* p) {
    uint32_t a;
    asm("{ .reg .u64 t; cvta.to.shared.u64 t, %1; cvt.u32.u64 %0, t; }"
        : "=r"(a) : "l"(p));
    return a;
}
#define SMEM_SWIZZLE_128B(o) ((o) ^ (((o) >> 3) & 0x70))

__device__ __forceinline__ void cp_async16(uint32_t saddr, const void* gptr) {
    asm volatile("cp.async.cg.shared.global [%0], [%1], 16;"
                 :: "r"(saddr), "l"(gptr));
}
__device__ __forceinline__ void ldmatrix_x4(uint32_t& r0, uint32_t& r1,
                                            uint32_t& r2, uint32_t& r3,
                                            uint32_t addr) {
    asm volatile("ldmatrix.sync.aligned.m8n8.x4.shared.b16 {%0,%1,%2,%3}, [%4];"
                 : "=r"(r0), "=r"(r1), "=r"(r2), "=r"(r3) : "r"(addr));
}
__device__ __forceinline__ void ldmatrix_x4_trans(uint32_t& r0, uint32_t& r1,
                                                  uint32_t& r2, uint32_t& r3,
                                                  uint32_t addr) {
    asm volatile("ldmatrix.sync.aligned.m8n8.x4.trans.shared.b16 {%0,%1,%2,%3}, [%4];"
                 : "=r"(r0), "=r"(r1), "=r"(r2), "=r"(r3) : "r"(addr));
}
__device__ __forceinline__ void mma_bf16(float* c,
                                         uint32_t a0, uint32_t a1, uint32_t a2, uint32_t a3,
                                         uint32_t b0, uint32_t b1) {
    asm volatile(
        "mma.sync.aligned.m16n8k16.row.col.f32.bf16.bf16.f32 "
        "{%0,%1,%2,%3}, {%4,%5,%6,%7}, {%8,%9}, {%0,%1,%2,%3};"
        : "+f"(c[0]), "+f"(c[1]), "+f"(c[2]), "+f"(c[3])
        : "r"(a0), "r"(a1), "r"(a2), "r"(a3), "r"(b0), "r"(b1));
}
__device__ __forceinline__ float ex2f(float x) {
    float r; asm("ex2.approx.f32 %0, %1;" : "=f"(r) : "f"(x)); return r;
}
__device__ __forceinline__ float sqrt_ap(float x) {
    float r; asm("sqrt.approx.f32 %0, %1;" : "=f"(r) : "f"(x)); return r;
}

// ---------------- bf16 warp-MMA NT GEMM -------------------------------------
// modes: 1 = fp32 C = res + gamma*(dot+bias)
//        3 = swiglu: cols are (h1,h2) interleaved pairs -> hs bf16 at col n0/2
//        4 = qkv: bf16 out routed to buffer n0>>9 at col n0&511
__global__ void __launch_bounds__(256) gemm_mma(
    const __nv_bfloat16* __restrict__ A,
    const __nv_bfloat16* __restrict__ Bw,
    const float* __restrict__ bias,
    float* __restrict__ C, __nv_bfloat16* __restrict__ Cb,
    int ldc, int Nc, int K,
    const float* __restrict__ res, const float* __restrict__ gamma, int mode)
{
    extern __shared__ char smem[];
    uint32_t sbase = smem_to_u32(smem);
    const int tid = threadIdx.x, lane = tid & 31, wid = tid >> 5;
    const int wm = wid & 1, wn = wid >> 1;
    const int bm = blockIdx.y * 128, bn = blockIdx.x * 64;

    const uint32_t STAGE = 24576u;
    const uint32_t BOFF  = 16384u;

    float acc[4][2][4];
    #pragma unroll
    for (int i = 0; i < 4; i++)
        #pragma unroll
        for (int j = 0; j < 2; j++)
            #pragma unroll
            for (int t = 0; t < 4; t++) acc[i][j][t] = 0.0f;

    const int lrow = tid >> 3;
    const int lcol = tid & 7;
    const int nch  = K >> 6;

    const int arow  = wm * 64 + (lane & 15);
    const int akoff = lane >> 4;
    const int brow  = wn * 16 + (lane & 7) + ((lane >> 4) << 3);
    const int bkoff = (lane >> 3) & 1;

    auto issue = [&](int c, int s) {
        uint32_t sb = sbase + (uint32_t)s * STAGE;
        #pragma unroll
        for (int i = 0; i < 4; i++) {
            int r = lrow + i * 32;
            uint32_t off = SMEM_SWIZZLE_128B((uint32_t)(r * 128 + lcol * 16));
            cp_async16(sb + off, A + (size_t)(bm + r) * K + c * 64 + lcol * 8);
        }
        #pragma unroll
        for (int i = 0; i < 2; i++) {
            int r = lrow + i * 32;
            uint32_t off = SMEM_SWIZZLE_128B((uint32_t)(r * 128 + lcol * 16));
            cp_async16(sb + BOFF + off, Bw + (size_t)(bn + r) * K + c * 64 + lcol * 8);
        }
        asm volatile("cp.async.commit_group;" ::: "memory");
    };

    issue(0, 0);
    for (int c = 0; c < nch; c++) {
        int s = c & 1;
        if (c + 1 < nch) {
            issue(c + 1, (c + 1) & 1);
            asm volatile("cp.async.wait_group 1;" ::: "memory");
        } else {
            asm volatile("cp.async.wait_group 0;" ::: "memory");
        }
        __syncthreads();

        uint32_t sa  = sbase + (uint32_t)s * STAGE;
        uint32_t sbb = sa + BOFF;
        #pragma unroll
        for (int ks = 0; ks < 4; ks++) {
            uint32_t a[4][4], b[4];
            #pragma unroll
            for (int mi = 0; mi < 4; mi++) {
                int r = arow + mi * 16;
                uint32_t addr = sa + SMEM_SWIZZLE_128B(
                    (uint32_t)(r * 128 + (2 * ks + akoff) * 16));
                ldmatrix_x4(a[mi][0], a[mi][1], a[mi][2], a[mi][3], addr);
            }
            {
                uint32_t addr = sbb + SMEM_SWIZZLE_128B(
                    (uint32_t)(brow * 128 + (2 * ks + bkoff) * 16));
                ldmatrix_x4(b[0], b[1], b[2], b[3], addr);
            }
            #pragma unroll
            for (int mi = 0; mi < 4; mi++) {
                mma_bf16(acc[mi][0], a[mi][0], a[mi][1], a[mi][2], a[mi][3], b[0], b[1]);
                mma_bf16(acc[mi][1], a[mi][0], a[mi][1], a[mi][2], a[mi][3], b[2], b[3]);
            }
        }
        __syncthreads();
    }

    int rbase = bm + wm * 64 + (lane >> 2);
    int cbase = bn + wn * 16 + 2 * (lane & 3);
    #pragma unroll
    for (int mi = 0; mi < 4; mi++) {
        int r0 = rbase + mi * 16;
        #pragma unroll
        for (int ni = 0; ni < 2; ni++) {
            int n0 = cbase + ni * 8;
            if (n0 < Nc) {
                float b0 = bias[n0], b1 = bias[n0 + 1];
                float v0 = acc[mi][ni][0] + b0, v1 = acc[mi][ni][1] + b1;
                float v2 = acc[mi][ni][2] + b0, v3 = acc[mi][ni][3] + b1;
                if (mode == 4) {
                    int buf = n0 >> 9, cc = n0 & 511;
                    __nv_bfloat16* dst = Cb + (size_t)buf * ((size_t)MTOT * DD)
                                            + (size_t)r0 * DD + cc;
                    *(__nv_bfloat162*)dst = __floats2bfloat162_rn(v0, v1);
                    *(__nv_bfloat162*)(dst + 8 * DD) = __floats2bfloat162_rn(v2, v3);
                } else if (mode == 3) {
                    int j = n0 >> 1;
                    float s0 = v0 / (1.0f + __expf(-v0));
                    float s2 = v2 / (1.0f + __expf(-v2));
                    Cb[(size_t)r0 * ldc + j]       = __float2bfloat16(s0 * v1);
                    Cb[(size_t)(r0 + 8) * ldc + j] = __float2bfloat16(s2 * v3);
                } else {
                    float g0 = gamma[n0], g1 = gamma[n0 + 1];
                    v0 = res[(size_t)r0 * ldc + n0]           + g0 * v0;
                    v1 = res[(size_t)r0 * ldc + n0 + 1]       + g1 * v1;
                    v2 = res[(size_t)(r0 + 8) * ldc + n0]     + g0 * v2;
                    v3 = res[(size_t)(r0 + 8) * ldc + n0 + 1] + g1 * v3;
                    *(float2*)&C[(size_t)r0 * ldc + n0]       = make_float2(v0, v1);
                    *(float2*)&C[(size_t)(r0 + 8) * ldc + n0] = make_float2(v2, v3);
                }
            }
        }
    }
}

// ---------------- LayerNorm -> bf16 (warp per row) --------------------------
__global__ void __launch_bounds__(128) ln_bf16_kernel(
    const float* __restrict__ x, const float* __restrict__ w,
    const float* __restrict__ b, __nv_bfloat16* __restrict__ out) {
    int warp = threadIdx.x >> 5, lane = threadIdx.x & 31;
    int row = blockIdx.x * 4 + warp;
    const float4* xr = (const float4*)(x + (size_t)row * DD);
    float4 v[4];
    float s = 0.0f, sq = 0.0f;
    #pragma unroll
    for (int i = 0; i < 4; i++) {
        v[i] = xr[lane + 32 * i];
        s  += v[i].x + v[i].y + v[i].z + v[i].w;
        sq += v[i].x*v[i].x + v[i].y*v[i].y + v[i].z*v[i].z + v[i].w*v[i].w;
    }
    #pragma unroll
    for (int o = 16; o; o >>= 1) {
        s  += __shfl_xor_sync(0xffffffffu, s,  o);
        sq += __shfl_xor_sync(0xffffffffu, sq, o);
    }
    float mean = s * (1.0f / DD);
    float var  = sq * (1.0f / DD) - mean * mean;
    float rstd = rsqrtf(var + 1e-5f);
    const float4* wr = (const float4*)w;
    const float4* br = (const float4*)b;
    uint2* orow = (uint2*)(out + (size_t)row * DD);
    #pragma unroll
    for (int i = 0; i < 4; i++) {
        float4 wv = wr[lane + 32 * i];
        float4 bv = br[lane + 32 * i];
        float o0 = (v[i].x - mean) * rstd * wv.x + bv.x;
        float o1 = (v[i].y - mean) * rstd * wv.y + bv.y;
        float o2 = (v[i].z - mean) * rstd * wv.z + bv.z;
        float o3 = (v[i].w - mean) * rstd * wv.w + bv.w;
        __nv_bfloat162 lo = __floats2bfloat162_rn(o0, o1);
        __nv_bfloat162 hi = __floats2bfloat162_rn(o2, o3);
        uint2 u; u.x = *(uint32_t*)&lo; u.y = *(uint32_t*)&hi;
        orow[lane + 32 * i] = u;
    }
}

// ---------------- weight converts -------------------------------------------
// packs q/k/v weights into one 1536x512 buffer + packed bias; o_w separate
__global__ void conv_qkv_kernel(const float* __restrict__ qw, const float* __restrict__ kw,
                                const float* __restrict__ vw, const float* __restrict__ ow,
                                const float* __restrict__ qb, const float* __restrict__ kb,
                                const float* __restrict__ vb2,
                                __nv_bfloat16* __restrict__ wqkv,
                                __nv_bfloat16* __restrict__ wo,
                                float* __restrict__ qkvb) {
    int idx = blockIdx.x * 256 + threadIdx.x;
    if (idx < DD * DD) {
        wqkv[idx]               = __float2bfloat16(qw[idx]);
        wqkv[idx +     DD * DD] = __float2bfloat16(kw[idx]);
        wqkv[idx + 2 * DD * DD] = __float2bfloat16(vw[idx]);
        wo[idx]                 = __float2bfloat16(ow[idx]);
    }
    if (idx < QKVN) {
        float bv = (idx < 512) ? qb[idx] : (idx < 1024) ? kb[idx - 512] : vb2[idx - 1024];
        qkvb[idx] = bv;
    }
}
// fc1: interleave h1/h2 rows (row 2j=fc1_w[j], row 2j+1=fc1_w[HID2+j]) + bias
__global__ void conv_fc1_kernel(const float* __restrict__ src, const float* __restrict__ bias,
                                __nv_bfloat16* __restrict__ dst, float* __restrict__ bdst) {
    size_t idx = (size_t)blockIdx.x * 256 + threadIdx.x;
    if (idx < (size_t)HIDNP * DD) {
        int r = (int)(idx / DD);
        int kk = (int)(idx - (size_t)r * DD);
        int j = r >> 1, half = r & 1;
        float v = (j < HID2) ? src[(size_t)(j + half * HID2) * DD + kk] : 0.0f;
        dst[idx] = __float2bfloat16(v);
    }
    if (idx < HIDNP) {
        int j = (int)idx >> 1, half = (int)idx & 1;
        bdst[idx] = (j < HID2) ? bias[j + half * HID2] : 0.0f;
    }
}
__global__ void conv_fc2_kernel(const float* __restrict__ src, __nv_bfloat16* __restrict__ dst) {
    size_t idx = (size_t)blockIdx.x * 256 + threadIdx.x;
    if (idx >= (size_t)DD * HID2P) return;
    int n = (int)(idx / HID2P);
    int k = (int)(idx - (size_t)n * HID2P);
    float v = (k < HID2) ? src[(size_t)n * HID2 + k] : 0.0f;
    dst[idx] = __float2bfloat16(v);
}

// ---------------- FA2 warp-MMA attention (all-bf16, double-buffered) --------
__global__ void __launch_bounds__(128) attn_mma(
    const __nv_bfloat16* __restrict__ q, const __nv_bfloat16* __restrict__ k,
    const __nv_bfloat16* __restrict__ vb, const float* __restrict__ coords,
    __nv_bfloat16* __restrict__ ctx)
{
    const int b = blockIdx.z, h = blockIdx.y, qt = blockIdx.x;
    const int tid = threadIdx.x, lane = tid & 31, wid = tid >> 5;

    __shared__ __align__(128) __nv_bfloat16 Ksm[2][64 * 64];
    __shared__ __align__(128) __nv_bfloat16 Vsm[2][64 * 64];
    __shared__ __align__(16) float2 Kc[2][64];

    const float LOG2E = 1.4426950408889634f;
    const float qscale = 0.125f * LOG2E;
    const float slope2 = exp2f(-(float)(h + 1)) * LOG2E;

    const int r0 = lane >> 2;
    const int gq0 = b * NTOK + qt * 64 + wid * 16 + r0;
    const int c0base = 2 * (lane & 3);

    uint32_t a[4][4];
    {
        const __nv_bfloat16* qp0 = q + (size_t)gq0 * DD + h * DHH;
        const __nv_bfloat16* qp1 = qp0 + 8 * DD;
        #pragma unroll
        for (int kt = 0; kt < 4; kt++) {
            a[kt][0] = *(const uint32_t*)(qp0 + kt * 16 + c0base);
            a[kt][1] = *(const uint32_t*)(qp1 + kt * 16 + c0base);
            a[kt][2] = *(const uint32_t*)(qp0 + kt * 16 + c0base + 8);
            a[kt][3] = *(const uint32_t*)(qp1 + kt * 16 + c0base + 8);
        }
    }
    float qx0 = coords[(size_t)gq0 * 2],       qy0 = coords[(size_t)gq0 * 2 + 1];
    float qx1 = coords[(size_t)(gq0 + 8) * 2], qy1 = coords[(size_t)(gq0 + 8) * 2 + 1];

    float o[8][4];
    #pragma unroll
    for (int j = 0; j < 8; j++)
        #pragma unroll
        for (int t = 0; t < 4; t++) o[j][t] = 0.0f;
    float m0 = -1e30f, m1 = -1e30f, l0 = 0.0f, l1 = 0.0f;

    uint32_t ksm_u = smem_to_u32(Ksm);
    uint32_t vsm_u = smem_to_u32(Vsm);
    uint32_t kc_u  = smem_to_u32(Kc);

    const int lr = tid >> 1, lh = tid & 1;
    const int brow = (lane & 7) + ((lane >> 4) << 3);
    const int bkoff = (lane >> 3) & 1;

    auto issue = [&](int kb, int s) {
        const __nv_bfloat16* kg = k  + (size_t)(b * NTOK + kb + lr) * DD + h * DHH + lh * 32;
        const __nv_bfloat16* vg = vb + (size_t)(b * NTOK + kb + lr) * DD + h * DHH + lh * 32;
        #pragma unroll
        for (int i = 0; i < 2; i++) {
            uint32_t off = SMEM_SWIZZLE_128B((uint32_t)(lr * 128 + lh * 64 + i * 32));
            cp_async16(ksm_u + (uint32_t)s * 8192u + off, kg + i * 16);
            cp_async16(ksm_u + (uint32_t)s * 8192u +
                       SMEM_SWIZZLE_128B((uint32_t)(lr * 128 + lh * 64 + i * 32 + 16)), kg + i * 16 + 8);
            cp_async16(vsm_u + (uint32_t)s * 8192u + off, vg + i * 16);
            cp_async16(vsm_u + (uint32_t)s * 8192u +
                       SMEM_SWIZZLE_128B((uint32_t)(lr * 128 + lh * 64 + i * 32 + 16)), vg + i * 16 + 8);
        }
        if (tid < 32) {
            cp_async16(kc_u + (uint32_t)s * 512u + (uint32_t)tid * 16u,
                       coords + (size_t)(b * NTOK + kb) * 2 + tid * 4);
        }
        asm volatile("cp.async.commit_group;" ::: "memory");
    };

    issue(0, 0);
    const int ntiles = NTOK / 64;
    for (int c = 0; c < ntiles; c++) {
        int s = c & 1;
        if (c + 1 < ntiles) {
            issue((c + 1) * 64, s ^ 1);
            asm volatile("cp.async.wait_group 1;" ::: "memory");
        } else {
            asm volatile("cp.async.wait_group 0;" ::: "memory");
        }
        __syncthreads();

        float sacc[8][4];
        #pragma unroll
        for (int j = 0; j < 8; j++)
            #pragma unroll
            for (int t = 0; t < 4; t++) sacc[j][t] = 0.0f;
        uint32_t kbase = ksm_u + (uint32_t)s * 8192u;
        #pragma unroll
        for (int ks = 0; ks < 4; ks++) {
            #pragma unroll
            for (int jj = 0; jj < 4; jj++) {
                uint32_t addr = kbase + SMEM_SWIZZLE_128B(
                    (uint32_t)((jj * 16 + brow) * 128 + (2 * ks + bkoff) * 16));
                uint32_t b0, b1, b2, b3;
                ldmatrix_x4(b0, b1, b2, b3, addr);
                mma_bf16(sacc[2 * jj],     a[ks][0], a[ks][1], a[ks][2], a[ks][3], b0, b1);
                mma_bf16(sacc[2 * jj + 1], a[ks][0], a[ks][1], a[ks][2], a[ks][3], b2, b3);
            }
        }

        float tm0 = -1e30f, tm1 = -1e30f;
        #pragma unroll
        for (int j = 0; j < 8; j++) {
            int cc = 8 * j + c0base;
            float2 k0 = Kc[s][cc], k1 = Kc[s][cc + 1];
            float dxa = qx0 - k0.x, dya = qy0 - k0.y;
            float dxb = qx0 - k1.x, dyb = qy0 - k1.y;
            float dxc = qx1 - k0.x, dyc = qy1 - k0.y;
            float dxd = qx1 - k1.x, dyd = qy1 - k1.y;
            sacc[j][0] = fmaf(sacc[j][0], qscale, -slope2 * sqrt_ap(dxa * dxa + dya * dya));
            sacc[j][1] = fmaf(sacc[j][1], qscale, -slope2 * sqrt_ap(dxb * dxb + dyb * dyb));
            sacc[j][2] = fmaf(sacc[j][2], qscale, -slope2 * sqrt_ap(dxc * dxc + dyc * dyc));
            sacc[j][3] = fmaf(sacc[j][3], qscale, -slope2 * sqrt_ap(dxd * dxd + dyd * dyd));
            tm0 = fmaxf(tm0, fmaxf(sacc[j][0], sacc[j][1]));
            tm1 = fmaxf(tm1, fmaxf(sacc[j][2], sacc[j][3]));
        }
        #pragma unroll
        for (int off = 1; off <= 2; off <<= 1) {
            tm0 = fmaxf(tm0, __shfl_xor_sync(0xffffffffu, tm0, off));
            tm1 = fmaxf(tm1, __shfl_xor_sync(0xffffffffu, tm1, off));
        }

        float mn0 = fmaxf(m0, tm0), mn1 = fmaxf(m1, tm1);
        float cr0 = ex2f(m0 - mn0), cr1 = ex2f(m1 - mn1);
        m0 = mn0; m1 = mn1;
        l0 *= cr0; l1 *= cr1;
        #pragma unroll
        for (int j = 0; j < 8; j++) {
            o[j][0] *= cr0; o[j][1] *= cr0;
            o[j][2] *= cr1; o[j][3] *= cr1;
        }
        #pragma unroll
        for (int j = 0; j < 8; j++) {
            float p0 = ex2f(sacc[j][0] - m0);
            float p1 = ex2f(sacc[j][1] - m0);
            float p2 = ex2f(sacc[j][2] - m1);
            float p3 = ex2f(sacc[j][3] - m1);
            l0 += p0 + p1; l1 += p2 + p3;
            sacc[j][0] = p0; sacc[j][1] = p1; sacc[j][2] = p2; sacc[j][3] = p3;
        }

        uint32_t vbase = vsm_u + (uint32_t)s * 8192u;
        #pragma unroll
        for (int t = 0; t < 4; t++) {
            __nv_bfloat162 h0 = __floats2bfloat162_rn(sacc[2*t][0],   sacc[2*t][1]);
            __nv_bfloat162 h1 = __floats2bfloat162_rn(sacc[2*t][2],   sacc[2*t][3]);
            __nv_bfloat162 h2 = __floats2bfloat162_rn(sacc[2*t+1][0], sacc[2*t+1][1]);
            __nv_bfloat162 h3 = __floats2bfloat162_rn(sacc[2*t+1][2], sacc[2*t+1][3]);
            uint32_t pa0 = *(uint32_t*)&h0, pa1 = *(uint32_t*)&h1;
            uint32_t pa2 = *(uint32_t*)&h2, pa3 = *(uint32_t*)&h3;
            #pragma unroll
            for (int g = 0; g < 4; g++) {
                uint32_t addr = vbase + SMEM_SWIZZLE_128B(
                    (uint32_t)((16 * t + (lane & 15)) * 128 + (16 * g + 8 * (lane >> 4)) * 2));
                uint32_t b0, b1, b2, b3;
                ldmatrix_x4_trans(b0, b1, b2, b3, addr);
                mma_bf16(o[2 * g],     pa0, pa1, pa2, pa3, b0, b1);
                mma_bf16(o[2 * g + 1], pa0, pa1, pa2, pa3, b2, b3);
            }
        }
        __syncthreads();
    }

    #pragma unroll
    for (int off = 1; off <= 2; off <<= 1) {
        l0 += __shfl_xor_sync(0xffffffffu, l0, off);
        l1 += __shfl_xor_sync(0xffffffffu, l1, off);
    }
    float inv0 = 1.0f / l0, inv1 = 1.0f / l1;
    __nv_bfloat16* crow0 = ctx + (size_t)gq0 * DD + h * DHH;
    __nv_bfloat16* crow1 = crow0 + 8 * DD;
    #pragma unroll
    for (int j = 0; j < 8; j++) {
        int d = 8 * j + c0base;
        *(__nv_bfloat162*)(crow0 + d) = __floats2bfloat162_rn(o[j][0] * inv0, o[j][1] * inv0);
        *(__nv_bfloat162*)(crow1 + d) = __floats2bfloat162_rn(o[j][2] * inv1, o[j][3] * inv1);
    }
}

// ---------------- launcher --------------------------------------------------
extern "C" void kernel_launch(void* const* d_in, const int* in_sizes, int n_in,
                              void* d_out, int out_size) {
    (void)in_sizes; (void)n_in; (void)out_size;
    const float* x      = (const float*)d_in[0];
    const float* coords = (const float*)d_in[1];
    const float* q_w    = (const float*)d_in[2];
    const float* q_b    = (const float*)d_in[3];
    const float* k_w    = (const float*)d_in[4];
    const float* k_b    = (const float*)d_in[5];
    const float* v_w    = (const float*)d_in[6];
    const float* v_b    = (const float*)d_in[7];
    const float* o_w    = (const float*)d_in[8];
    const float* o_b    = (const float*)d_in[9];
    const float* gamma1 = (const float*)d_in[10];
    const float* ln1_w  = (const float*)d_in[11];
    const float* ln1_b  = (const float*)d_in[12];
    const float* fc1_w  = (const float*)d_in[13];
    const float* fc1_b  = (const float*)d_in[14];
    const float* fc2_w  = (const float*)d_in[15];
    const float* fc2_b  = (const float*)d_in[16];
    const float* gamma2 = (const float*)d_in[17];
    const float* ln2_w  = (const float*)d_in[18];
    const float* ln2_b  = (const float*)d_in[19];
    float* out = (float*)d_out;

    __nv_bfloat16 *xn, *xn2, *ctxb, *qkv, *wqkv, *wo, *fc1w, *fc2w, *hsb;
    float *x1, *qkvb, *fc1b;
    cudaGetSymbolAddress((void**)&xn,   g_xn_bf);
    cudaGetSymbolAddress((void**)&xn2,  g_xn2_bf);
    cudaGetSymbolAddress((void**)&ctxb, g_ctx_bf);
    cudaGetSymbolAddress((void**)&qkv,  g_qkv_bf);
    cudaGetSymbolAddress((void**)&wqkv, g_wqkv_bf);
    cudaGetSymbolAddress((void**)&wo,   g_wo_bf);
    cudaGetSymbolAddress((void**)&fc1w, g_fc1w_bf);
    cudaGetSymbolAddress((void**)&fc2w, g_fc2w_bf);
    cudaGetSymbolAddress((void**)&hsb,  g_hs_bf);
    cudaGetSymbolAddress((void**)&x1,   g_x1);
    cudaGetSymbolAddress((void**)&qkvb, g_qkvb);
    cudaGetSymbolAddress((void**)&fc1b, g_fc1b);

    const int SMEM_GEMM = 49152;

    // weight conversions
    conv_qkv_kernel<<<(DD * DD + 255) / 256, 256>>>(q_w, k_w, v_w, o_w, q_b, k_b, v_b,
                                                    wqkv, wo, qkvb);
    {
        size_t n2 = (size_t)HIDNP * DD;
        conv_fc1_kernel<<<(int)((n2 + 255) / 256), 256>>>(fc1_w, fc1_b, fc1w, fc1b);
        size_t n3 = (size_t)DD * HID2P;
        conv_fc2_kernel<<<(int)((n3 + 255) / 256), 256>>>(fc2_w, fc2w);
    }

    ln_bf16_kernel<<<MTOT / 4, 128>>>(x, ln1_w, ln1_b, xn);

    // fused QKV projection (bf16 routed outputs)
    dim3 gqkv(QKVN / 64, MTOT / 128);
    gemm_mma<<<gqkv, 256, SMEM_GEMM>>>(xn, wqkv, qkvb, nullptr, qkv, DD, QKVN, DD,
                                       nullptr, nullptr, 4);

    // FA2 attention
    dim3 gattn(NTOK / 64, HH, BB);
    attn_mma<<<gattn, 128>>>(qkv, qkv + (size_t)MTOT * DD, qkv + 2 * (size_t)MTOT * DD,
                             coords, ctxb);

    // O projection + residual1
    dim3 gproj(DD / 64, MTOT / 128);
    gemm_mma<<<gproj, 256, SMEM_GEMM>>>(ctxb, wo, o_b, x1, nullptr, DD, DD, DD, x, gamma1, 1);

    ln_bf16_kernel<<<MTOT / 4, 128>>>(x1, ln2_w, ln2_b, xn2);

    // fc1 + fused SwiGLU -> hs bf16
    dim3 gfc1(HIDNP / 64, MTOT / 128);
    gemm_mma<<<gfc1, 256, SMEM_GEMM>>>(xn2, fc1w, fc1b, nullptr, hsb, HID2P, HIDNP, DD,
                                       nullptr, nullptr, 3);

    // fc2 + residual2 -> out
    gemm_mma<<<gproj, 256, SMEM_GEMM>>>(hsb, fc2w, fc2_b, out, nullptr, DD, DD, HID2P,
                                        x1, gamma2, 1);
}